// round 5
// baseline (speedup 1.0000x reference)
#include <cuda_runtime.h>

#define HID   2048
#define NEXP  64
#define NTOK  16384
#define SINK_TOL 1e-4
#define MAX_ITERS 512
#define GRIDB 148
#define TPB   512
#define NW    (TPB / 32)
#define TOKB  111   // ceil(NTOK / GRIDB); 148*111 = 16428 >= 16384

// libdevice exp — what XLA GPU emits for jnp.exp, immune to fast-math rewrite.
extern "C" __device__ float __nv_expf(float);

typedef unsigned long long u64;

// packed f32x2 helpers — each half is IEEE fma.rn/add.rn.f32, bitwise equal
// to the scalar chain.
__device__ __forceinline__ u64 fma2(u64 a, u64 b, u64 c) {
    u64 d; asm("fma.rn.f32x2 %0,%1,%2,%3;" : "=l"(d) : "l"(a), "l"(b), "l"(c)); return d;
}
__device__ __forceinline__ u64 add2(u64 a, u64 b) {
    u64 d; asm("add.rn.f32x2 %0,%1,%2;" : "=l"(d) : "l"(a), "l"(b)); return d;
}
__device__ __forceinline__ void unpack2(u64 v, float& lo, float& hi) {
    asm("mov.b64 {%0,%1},%2;" : "=f"(lo), "=f"(hi) : "l"(v));
}
__device__ __forceinline__ float frcp_approx(float x) {
    float r; asm("rcp.approx.f32 %0,%1;" : "=f"(r) : "f"(x)); return r;
}

// Scratch (static device arrays — no allocations).
__device__ unsigned long long g_bar = 0ULL;              // monotonic grid barrier
__device__ float  g_C[(size_t)NTOK * NEXP];              // exp(logits) f32, 4 MB
__device__ double g_colsum[MAX_ITERS * NEXP];            // per-iteration column sums (f64)

// ---------------------------------------------------------------------------
// Kernel 1: logits GEMM via packed FFMA2 (fma.rn.f32x2).  Same chunked
// accumulation as R4 (f32 chain inside BK=64 chunk, chunk partials added to
// second-level f32 accumulator) -> bitwise-identical logits to R4.
// A tile stored duplicated (a,a) so the broadcast operand is one LDS.64.
// ---------------------------------------------------------------------------
#define BM 64
#define BK 64
#define ALD 130   // As_dup row stride in floats (8B-aligned rows)
#define LDPAD 68  // Bs row stride in floats (16B-aligned)

__global__ void __launch_bounds__(256)
gemm_exp_kernel(const float* __restrict__ X, const float* __restrict__ W)
{
    __shared__ float Ad[BM][ALD];     // duplicated A: Ad[m][2k]=Ad[m][2k+1]=a
    __shared__ float Bs[BK][LDPAD];   // [k][expert]

    int tid = threadIdx.x;
    int tx  = tid & 15;               // expert group (4 experts)
    int ty  = tid >> 4;               // token group  (4 tokens)
    int m0  = blockIdx.x * BM;

    u64 hi[4][2];
#pragma unroll
    for (int i = 0; i < 4; i++) { hi[i][0] = 0ULL; hi[i][1] = 0ULL; }

    for (int k0 = 0; k0 < HID; k0 += BK) {
        // A tile: 64x64 floats = 1024 float4, 4 per thread, duplicated scatter
#pragma unroll
        for (int j = 0; j < 4; j++) {
            int idx = tid + j * 256;
            int m   = idx >> 4;
            int kq  = (idx & 15) << 2;
            float4 v = *(const float4*)(X + (size_t)(m0 + m) * HID + k0 + kq);
            float* row = &Ad[m][kq << 1];
            *(float2*)(row + 0) = make_float2(v.x, v.x);
            *(float2*)(row + 2) = make_float2(v.y, v.y);
            *(float2*)(row + 4) = make_float2(v.z, v.z);
            *(float2*)(row + 6) = make_float2(v.w, v.w);
        }
        // B tile: 64 experts x 64 k = 1024 float4, 4 per thread, k-major scatter
#pragma unroll
        for (int j = 0; j < 4; j++) {
            int idx = tid + j * 256;
            int e   = idx >> 4;
            int kq  = (idx & 15) << 2;
            float4 v = *(const float4*)(W + (size_t)e * HID + k0 + kq);
            Bs[kq + 0][e] = v.x; Bs[kq + 1][e] = v.y;
            Bs[kq + 2][e] = v.z; Bs[kq + 3][e] = v.w;
        }
        __syncthreads();

        u64 accf[4][2];
#pragma unroll
        for (int i = 0; i < 4; i++) { accf[i][0] = 0ULL; accf[i][1] = 0ULL; }

#pragma unroll 16
        for (int k = 0; k < BK; k++) {
            ulonglong2 bv = *(const ulonglong2*)&Bs[k][tx * 4];
#pragma unroll
            for (int i = 0; i < 4; i++) {
                u64 ap = *(const u64*)&Ad[ty * 4 + i][k << 1];
                accf[i][0] = fma2(ap, bv.x, accf[i][0]);
                accf[i][1] = fma2(ap, bv.y, accf[i][1]);
            }
        }
#pragma unroll
        for (int i = 0; i < 4; i++) {
            hi[i][0] = add2(hi[i][0], accf[i][0]);
            hi[i][1] = add2(hi[i][1], accf[i][1]);
        }
        __syncthreads();
    }

#pragma unroll
    for (int i = 0; i < 4; i++) {
        size_t t = (size_t)(m0 + ty * 4 + i);
        float l0, l1, l2, l3;
        unpack2(hi[i][0], l0, l1);
        unpack2(hi[i][1], l2, l3);
        float4 o;
        o.x = __nv_expf(l0); o.y = __nv_expf(l1);
        o.z = __nv_expf(l2); o.w = __nv_expf(l3);
        *(float4*)&g_C[t * NEXP + tx * 4] = o;
    }
}

// ---------------------------------------------------------------------------
// Grid barrier: monotonic 64-bit counter; 148 co-resident CTAs (1/SM).
// Counter is a multiple of GRIDB at launch boundaries -> graph-replay safe.
// ---------------------------------------------------------------------------
__device__ __forceinline__ void grid_barrier()
{
    __syncthreads();
    if (threadIdx.x == 0) {
        __threadfence();
        unsigned long long my = atomicAdd(&g_bar, 1ULL);
        unsigned long long target = (my / GRIDB + 1ULL) * GRIDB;
        for (;;) {
            unsigned long long cur;
            asm volatile("ld.global.acquire.gpu.u64 %0, [%1];" : "=l"(cur) : "l"(&g_bar));
            if (cur >= target) break;
        }
    }
    __syncthreads();
}

__device__ __forceinline__ double warp_tree_add64(double s)
{
#pragma unroll
    for (int off = 16; off; off >>= 1)
        s += __shfl_xor_sync(0xffffffffu, s, off);
    return s;
}

// ---------------------------------------------------------------------------
// Kernel 2: persistent Sinkhorn + top-2 + softmax-gather.
// Row pass f32 (d0 via rcp.approx * 2^-14 — per-token ~1e-7 error averages to
// ~1e-9 in the colsum).  d1 / err / final ranking stay fp64.  Post-barrier
// phase fused into warp 0 with a single __syncthreads.
// ---------------------------------------------------------------------------
__global__ void __launch_bounds__(TPB)
sinkhorn_kernel(float* __restrict__ out, int out_size)
{
    __shared__ float  Cs[TOKB * NEXP];        // ~27.8 KB
    __shared__ double d1d[NEXP];              // current d1 (f64 master)
    __shared__ double d1pd[NEXP];             // d1 at entry of last iteration
    __shared__ float  d1f[NEXP];              // f32 mirror for the row pass
    __shared__ float  warp_part[NW][NEXP];    // 4 KB
    __shared__ double s_err;

    const int tid  = threadIdx.x;
    const int bid  = blockIdx.x;
    const int lane = tid & 31;
    const int w    = tid >> 5;
    const int tok0 = bid * TOKB;
    const int ntok = min(TOKB, NTOK - tok0);

    for (int i = bid * TPB + tid; i < MAX_ITERS * NEXP; i += GRIDB * TPB)
        g_colsum[i] = 0.0;
    {   // vectorized stage of this block's C slice
        const float4* src = (const float4*)(g_C + (size_t)tok0 * NEXP);
        float4* dst = (float4*)Cs;
        for (int i = tid; i < ntok * (NEXP / 4); i += TPB) dst[i] = src[i];
    }
    if (tid < NEXP) { d1d[tid] = 1.0; d1pd[tid] = 1.0; d1f[tid] = 1.f; }
    grid_barrier();   // colsum zeros globally visible

    const float  INVN0F = 1.0f / (float)NTOK;   // 2^-14 exact
    const float  EPSF   = 1e-8f;
    const double INVN1D = 1.0 / (double)NEXP;
    const double EPSD   = (double)1e-8f;

    for (int it = 0; it < MAX_ITERS; it++) {
        float d1a = d1f[lane];
        float d1c = d1f[lane + 32];
        float p0 = 0.f, p1 = 0.f;
        for (int t = w; t < ntok; t += NW) {
            float c0 = Cs[t * NEXP + lane];
            float c1 = Cs[t * NEXP + lane + 32];
            float s  = fmaf(d1a, c0, d1c * c1);
#pragma unroll
            for (int off = 16; off; off >>= 1)
                s += __shfl_xor_sync(0xffffffffu, s, off);
            float d0 = frcp_approx(s + EPSF) * INVN0F;   // exact pow2 scale
            p0 = fmaf(d0, c0, p0);
            p1 = fmaf(d0, c1, p1);
        }
        warp_part[w][lane]      = p0;
        warp_part[w][lane + 32] = p1;
        __syncthreads();
        if (tid < NEXP) {
            double sum = 0.0;
#pragma unroll
            for (int ww = 0; ww < NW; ww++) sum += (double)warp_part[ww][tid];
            atomicAdd(&g_colsum[it * NEXP + tid], sum);
        }
        grid_barrier();

        // fused post-barrier phase: warp 0 only, single syncthreads after
        if (w == 0) {
            double cs0 = g_colsum[it * NEXP + lane];
            double cs1 = g_colsum[it * NEXP + lane + 32];
            double v0  = INVN1D / (cs0 + EPSD);
            double v1  = INVN1D / (cs1 + EPSD);
            double o0  = d1d[lane];
            double o1  = d1d[lane + 32];
            double s   = warp_tree_add64(fabs(o0 - v0) + fabs(o1 - v1));
            d1pd[lane]      = o0;  d1pd[lane + 32] = o1;
            d1d[lane]       = v0;  d1d[lane + 32]  = v1;
            d1f[lane]       = (float)v0;
            d1f[lane + 32]  = (float)v1;
            if (lane == 0) s_err = s * INVN1D;
        }
        __syncthreads();
        if (s_err <= SINK_TOL) break;   // identical decision in every block
    }

    // ---- final: top-2 of d1_final*C*d0_final (fp64);  scores = C/rowsum(C) --
    const double INVN0D = 1.0 / (double)NTOK;
    double d1a = d1d[lane], d1c = d1d[lane + 32];
    double dpa = d1pd[lane], dpc = d1pd[lane + 32];
    for (int t = w; t < ntok; t += NW) {
        double c0 = (double)Cs[t * NEXP + lane];
        double c1 = (double)Cs[t * NEXP + lane + 32];
        // d0 uses d1 entering the last executed iteration (= while_loop state)
        double sr = warp_tree_add64(dpa * c0 + dpc * c1);
        double rs = warp_tree_add64(c0 + c1);
        double d0 = INVN0D / (sr + EPSD);
        double v0 = (d1a * c0) * d0;
        double v1 = (d1c * c1) * d0;

        // argmax #1, ties -> lower index (jax top_k convention)
        double mv; int mi;
        if (v0 >= v1) { mv = v0; mi = lane; } else { mv = v1; mi = lane + 32; }
#pragma unroll
        for (int off = 16; off; off >>= 1) {
            double ov = __shfl_xor_sync(0xffffffffu, mv, off);
            int    oi = __shfl_xor_sync(0xffffffffu, mi, off);
            if (ov > mv || (ov == mv && oi < mi)) { mv = ov; mi = oi; }
        }
        // argmax #2 (exclude mi)
        double u0 = (lane      == mi) ? -1e308 : v0;
        double u1 = (lane + 32 == mi) ? -1e308 : v1;
        double mv2; int mi2;
        if (u0 >= u1) { mv2 = u0; mi2 = lane; } else { mv2 = u1; mi2 = lane + 32; }
#pragma unroll
        for (int off = 16; off; off >>= 1) {
            double ov = __shfl_xor_sync(0xffffffffu, mv2, off);
            int    oi = __shfl_xor_sync(0xffffffffu, mi2, off);
            if (ov > mv2 || (ov == mv2 && oi < mi2)) { mv2 = ov; mi2 = oi; }
        }

        if (lane == 0) {
            int tg = tok0 + t;
            float s0 = (float)((double)Cs[t * NEXP + mi]  / rs);
            float s1 = (float)((double)Cs[t * NEXP + mi2] / rs);
            if (out_size >= 4 * NTOK) {
                out[(size_t)tg * 2 + 0] = s0;
                out[(size_t)tg * 2 + 1] = s1;
                out[(size_t)2 * NTOK + tg * 2 + 0] = (float)mi;
                out[(size_t)2 * NTOK + tg * 2 + 1] = (float)mi2;
            } else {
                out[(size_t)tg * 2 + 0] = s0;
                out[(size_t)tg * 2 + 1] = s1;
            }
        }
    }
}

// ---------------------------------------------------------------------------
extern "C" void kernel_launch(void* const* d_in, const int* in_sizes, int n_in,
                              void* d_out, int out_size)
{
    const float* X = (const float*)d_in[0];
    const float* W = (const float*)d_in[1];
    if (n_in >= 2 && in_sizes[0] == NEXP * HID) {   // defensive input-order check
        X = (const float*)d_in[1];
        W = (const float*)d_in[0];
    }
    gemm_exp_kernel<<<NTOK / BM, 256>>>(X, W);
    sinkhorn_kernel<<<GRIDB, TPB>>>((float*)d_out, out_size);
}

// round 6
// speedup vs baseline: 1.3880x; 1.3880x over previous
#include <cuda_runtime.h>

#define HID   2048
#define NEXP  64
#define NTOK  16384
#define SINK_TOL 1e-4
#define MAX_ITERS 512
#define GRIDB 148
#define TPB   448
#define NW    14          // warps per block
#define TOKB  111         // tokens owned per block; 148*111 = 16428 >= 16384
#define TOKP  112         // padded token slots (28 groups x 4)
#define BK    64
#define NCHUNK (HID / BK) // 32
#define LD    68          // smem row stride (floats)

// libdevice exp — what XLA GPU emits for jnp.exp, immune to fast-math rewrite.
extern "C" __device__ float __nv_expf(float);

__device__ __forceinline__ float frcp_approx(float x) {
    float r; asm("rcp.approx.f32 %0,%1;" : "=f"(r) : "f"(x)); return r;
}

// Scratch (static device arrays — no allocations).
__device__ unsigned long long g_bar = 0ULL;              // monotonic grid barrier
__device__ double g_colsum[MAX_ITERS * NEXP];            // per-iteration column sums

// ---- shared memory overlay: GEMM tiles, then sinkhorn state ----------------
struct SmemGemm {
    float As[TOKP][LD];   // 112 x 68 floats = 30464 B
    float Bs[BK][LD];     //  64 x 68 floats = 17408 B   (total 47872 B)
};
struct SmemSink {
    float  Cs[TOKP * NEXP];       // 28672 B
    float  warp_part[NW][NEXP];   //  3584 B
    double d1d[NEXP];             // current d1 (f64 master)
    double d1pd[NEXP];            // d1 entering last iteration
    float  d1f[NEXP];             // f32 mirror for row pass
    double s_err;
};
union SmemU { SmemGemm g; SmemSink s; };

__device__ __forceinline__ void grid_barrier()
{
    __syncthreads();
    if (threadIdx.x == 0) {
        __threadfence();
        unsigned long long my = atomicAdd(&g_bar, 1ULL);
        unsigned long long target = (my / GRIDB + 1ULL) * GRIDB;
        for (;;) {
            unsigned long long cur;
            asm volatile("ld.global.acquire.gpu.u64 %0, [%1];" : "=l"(cur) : "l"(&g_bar));
            if (cur >= target) break;
        }
    }
    __syncthreads();
}

__device__ __forceinline__ double warp_tree_add64(double s)
{
#pragma unroll
    for (int off = 16; off; off >>= 1)
        s += __shfl_xor_sync(0xffffffffu, s, off);
    return s;
}

// ---------------------------------------------------------------------------
// One persistent kernel: per-block GEMM for its 111 tokens (logits -> exp ->
// Cs in smem), then Sinkhorn iterations (global colsum via atomics + grid
// barrier), then top-2 + softmax-gather.  GEMM arithmetic is bitwise
// identical to R4 (f32 FFMA chain per BK=64 chunk, chunk partials summed
// into a second-level f32 accumulator).
// ---------------------------------------------------------------------------
__global__ void __launch_bounds__(TPB)
fused_router_kernel(const float* __restrict__ X, const float* __restrict__ W,
                    float* __restrict__ out, int out_size)
{
    __shared__ SmemU sm;

    const int tid  = threadIdx.x;
    const int bid  = blockIdx.x;
    const int lane = tid & 31;
    const int w    = tid >> 5;
    const int tx   = tid & 15;        // expert quad: experts tx*4 .. tx*4+3
    const int ty   = tid >> 4;        // token group 0..27: tokens ty*4 .. +3
    const int tok0 = bid * TOKB;
    const int ntok = min(TOKB, NTOK - tok0);

    // zero this launch's colsum slice (visible after the first grid_barrier)
    for (int i = bid * TPB + tid; i < MAX_ITERS * NEXP; i += GRIDB * TPB)
        g_colsum[i] = 0.0;

    // ---------------- phase A: GEMM + exp -> sm.s.Cs -----------------------
    // A-tile load map: 112 rows x 16 quads = 1792 = 448*4
    int    am[4], akq[4];
    size_t arow[4];
#pragma unroll
    for (int j = 0; j < 4; j++) {
        int idx = tid + j * TPB;
        am[j]  = idx >> 4;
        akq[j] = (idx & 15) << 2;
        int g  = tok0 + am[j];
        if (g > NTOK - 1) g = NTOK - 1;          // clamp pad rows
        arow[j] = (size_t)g * HID;
    }
    // B-tile load map: 64 x 16 quads = 1024 -> 3 per thread, guarded
    int be[3], bkq[3]; bool bok[3];
#pragma unroll
    for (int j = 0; j < 3; j++) {
        int idx = tid + j * TPB;
        bok[j] = idx < 1024;
        be[j]  = idx >> 4;
        bkq[j] = (idx & 15) << 2;
    }

    float4 av[4], bv[3];
#pragma unroll
    for (int j = 0; j < 4; j++) av[j] = *(const float4*)(X + arow[j] + akq[j]);
#pragma unroll
    for (int j = 0; j < 3; j++)
        if (bok[j]) bv[j] = *(const float4*)(W + (size_t)be[j] * HID + bkq[j]);

    float hi[4][4];
#pragma unroll
    for (int i = 0; i < 4; i++)
#pragma unroll
        for (int jj = 0; jj < 4; jj++) hi[i][jj] = 0.f;

    for (int c = 0; c < NCHUNK; c++) {
        // commit staged tile to smem
#pragma unroll
        for (int j = 0; j < 4; j++)
            *(float4*)&sm.g.As[am[j]][akq[j]] = av[j];
#pragma unroll
        for (int j = 0; j < 3; j++)
            if (bok[j]) {
                sm.g.Bs[bkq[j] + 0][be[j]] = bv[j].x;
                sm.g.Bs[bkq[j] + 1][be[j]] = bv[j].y;
                sm.g.Bs[bkq[j] + 2][be[j]] = bv[j].z;
                sm.g.Bs[bkq[j] + 3][be[j]] = bv[j].w;
            }
        __syncthreads();

        // prefetch next chunk into registers (overlaps with compute)
        if (c + 1 < NCHUNK) {
            int k0 = (c + 1) * BK;
#pragma unroll
            for (int j = 0; j < 4; j++)
                av[j] = *(const float4*)(X + arow[j] + k0 + akq[j]);
#pragma unroll
            for (int j = 0; j < 3; j++)
                if (bok[j]) bv[j] = *(const float4*)(W + (size_t)be[j] * HID + k0 + bkq[j]);
        }

        float accf[4][4];
#pragma unroll
        for (int i = 0; i < 4; i++)
#pragma unroll
            for (int jj = 0; jj < 4; jj++) accf[i][jj] = 0.f;

#pragma unroll 16
        for (int k = 0; k < BK; k++) {
            float a[4];
#pragma unroll
            for (int i = 0; i < 4; i++) a[i] = sm.g.As[ty * 4 + i][k];
            float4 b4 = *(const float4*)&sm.g.Bs[k][tx * 4];
            float b[4] = {b4.x, b4.y, b4.z, b4.w};
#pragma unroll
            for (int i = 0; i < 4; i++)
#pragma unroll
                for (int jj = 0; jj < 4; jj++)
                    accf[i][jj] = fmaf(a[i], b[jj], accf[i][jj]);
        }
#pragma unroll
        for (int i = 0; i < 4; i++)
#pragma unroll
            for (int jj = 0; jj < 4; jj++) hi[i][jj] += accf[i][jj];
        __syncthreads();   // all reads of As/Bs done before Cs overlay write
    }

    // epilogue: exp(logits) straight into the sinkhorn tile (aliases As/Bs)
#pragma unroll
    for (int i = 0; i < 4; i++) {
        int slot = ty * 4 + i;
        float4 o;
        o.x = __nv_expf(hi[i][0]); o.y = __nv_expf(hi[i][1]);
        o.z = __nv_expf(hi[i][2]); o.w = __nv_expf(hi[i][3]);
        *(float4*)&sm.s.Cs[slot * NEXP + tx * 4] = o;
    }
    if (tid < NEXP) { sm.s.d1d[tid] = 1.0; sm.s.d1pd[tid] = 1.0; sm.s.d1f[tid] = 1.f; }
    grid_barrier();   // Cs ready block-locally; colsum zeros globally visible

    // ---------------- phase B: Sinkhorn iterations --------------------------
    const float  INVN0F = 1.0f / (float)NTOK;   // 2^-14 exact
    const float  EPSF   = 1e-8f;
    const double INVN1D = 1.0 / (double)NEXP;
    const double EPSD   = (double)1e-8f;

    for (int it = 0; it < MAX_ITERS; it++) {
        float d1a = sm.s.d1f[lane];
        float d1c = sm.s.d1f[lane + 32];
        float p0 = 0.f, p1 = 0.f;
        for (int t = w; t < ntok; t += NW) {
            float c0 = sm.s.Cs[t * NEXP + lane];
            float c1 = sm.s.Cs[t * NEXP + lane + 32];
            float s  = fmaf(d1a, c0, d1c * c1);
#pragma unroll
            for (int off = 16; off; off >>= 1)
                s += __shfl_xor_sync(0xffffffffu, s, off);
            float d0 = frcp_approx(s + EPSF) * INVN0F;   // exact pow2 scale
            p0 = fmaf(d0, c0, p0);
            p1 = fmaf(d0, c1, p1);
        }
        sm.s.warp_part[w][lane]      = p0;
        sm.s.warp_part[w][lane + 32] = p1;
        __syncthreads();
        if (tid < NEXP) {
            double sum = 0.0;
#pragma unroll
            for (int ww = 0; ww < NW; ww++) sum += (double)sm.s.warp_part[ww][tid];
            atomicAdd(&g_colsum[it * NEXP + tid], sum);
        }
        grid_barrier();

        // fused post-barrier phase: warp 0 only, single __syncthreads after
        if (w == 0) {
            double cs0 = g_colsum[it * NEXP + lane];
            double cs1 = g_colsum[it * NEXP + lane + 32];
            double v0  = INVN1D / (cs0 + EPSD);
            double v1  = INVN1D / (cs1 + EPSD);
            double o0  = sm.s.d1d[lane];
            double o1  = sm.s.d1d[lane + 32];
            double s   = warp_tree_add64(fabs(o0 - v0) + fabs(o1 - v1));
            sm.s.d1pd[lane]      = o0;  sm.s.d1pd[lane + 32] = o1;
            sm.s.d1d[lane]       = v0;  sm.s.d1d[lane + 32]  = v1;
            sm.s.d1f[lane]       = (float)v0;
            sm.s.d1f[lane + 32]  = (float)v1;
            if (lane == 0) sm.s.s_err = s * INVN1D;
        }
        __syncthreads();
        if (sm.s.s_err <= SINK_TOL) break;   // identical decision in every block
    }

    // ---------------- phase C: top-2 (fp64) + softmax-gather ----------------
    const double INVN0D = 1.0 / (double)NTOK;
    double d1a = sm.s.d1d[lane],  d1c = sm.s.d1d[lane + 32];
    double dpa = sm.s.d1pd[lane], dpc = sm.s.d1pd[lane + 32];
    for (int t = w; t < ntok; t += NW) {
        double c0 = (double)sm.s.Cs[t * NEXP + lane];
        double c1 = (double)sm.s.Cs[t * NEXP + lane + 32];
        // d0 uses d1 entering the last executed iteration (= while_loop state)
        double sr = warp_tree_add64(dpa * c0 + dpc * c1);
        double rs = warp_tree_add64(c0 + c1);
        double d0 = INVN0D / (sr + EPSD);
        double v0 = (d1a * c0) * d0;
        double v1 = (d1c * c1) * d0;

        // argmax #1, ties -> lower index (jax top_k convention)
        double mv; int mi;
        if (v0 >= v1) { mv = v0; mi = lane; } else { mv = v1; mi = lane + 32; }
#pragma unroll
        for (int off = 16; off; off >>= 1) {
            double ov = __shfl_xor_sync(0xffffffffu, mv, off);
            int    oi = __shfl_xor_sync(0xffffffffu, mi, off);
            if (ov > mv || (ov == mv && oi < mi)) { mv = ov; mi = oi; }
        }
        // argmax #2 (exclude mi)
        double u0 = (lane      == mi) ? -1e308 : v0;
        double u1 = (lane + 32 == mi) ? -1e308 : v1;
        double mv2; int mi2;
        if (u0 >= u1) { mv2 = u0; mi2 = lane; } else { mv2 = u1; mi2 = lane + 32; }
#pragma unroll
        for (int off = 16; off; off >>= 1) {
            double ov = __shfl_xor_sync(0xffffffffu, mv2, off);
            int    oi = __shfl_xor_sync(0xffffffffu, mi2, off);
            if (ov > mv2 || (ov == mv2 && oi < mi2)) { mv2 = ov; mi2 = oi; }
        }

        if (lane == 0) {
            int tg = tok0 + t;
            float s0 = (float)((double)sm.s.Cs[t * NEXP + mi]  / rs);
            float s1 = (float)((double)sm.s.Cs[t * NEXP + mi2] / rs);
            if (out_size >= 4 * NTOK) {
                out[(size_t)tg * 2 + 0] = s0;
                out[(size_t)tg * 2 + 1] = s1;
                out[(size_t)2 * NTOK + tg * 2 + 0] = (float)mi;
                out[(size_t)2 * NTOK + tg * 2 + 1] = (float)mi2;
            } else {
                out[(size_t)tg * 2 + 0] = s0;
                out[(size_t)tg * 2 + 1] = s1;
            }
        }
    }
}

// ---------------------------------------------------------------------------
extern "C" void kernel_launch(void* const* d_in, const int* in_sizes, int n_in,
                              void* d_out, int out_size)
{
    const float* X = (const float*)d_in[0];
    const float* W = (const float*)d_in[1];
    if (n_in >= 2 && in_sizes[0] == NEXP * HID) {   // defensive input-order check
        X = (const float*)d_in[1];
        W = (const float*)d_in[0];
    }
    fused_router_kernel<<<GRIDB, TPB>>>(X, W, (float*)d_out, out_size);
}

// round 8
// speedup vs baseline: 1.4837x; 1.0689x over previous
#include <cuda_runtime.h>
#include <cuda_bf16.h>
#include <cstdint>

#define HID   2048
#define NEXP  64
#define NTOK  16384
#define SINK_TOL 1e-4
#define MAX_ITERS 512
#define GRIDB 128
#define TPB   512
#define NW    16
#define TOKB  128          // 16384 = 128 * 128 exactly
#define BKC   64           // k-chunk (elems) -> 128 B bf16 rows (SW128 atom)
#define NCHUNK (HID / BKC) // 32

// dynamic smem layout (bytes): three A splits, three B splits
#define TILE_A 16384       // 128 rows x 128 B
#define TILE_B 8192        //  64 rows x 128 B
#define SM_A1  1024
#define SM_A2  (SM_A1 + TILE_A)
#define SM_A3  (SM_A2 + TILE_A)
#define SM_B1  (SM_A3 + TILE_A)
#define SM_B2  (SM_B1 + TILE_B)
#define SM_B3  (SM_B2 + TILE_B)
#define DSM_TOTAL (SM_B3 + TILE_B)
#define SM_CS  1024        // Cs overlay (32 KB) after GEMM completes

extern "C" __device__ float __nv_expf(float);

__device__ __forceinline__ float frcp_approx(float x) {
    float r; asm("rcp.approx.f32 %0,%1;" : "=f"(r) : "f"(x)); return r;
}
__device__ __forceinline__ uint32_t smem_u32(const void* p) {
    uint32_t a;
    asm("{ .reg .u64 t; cvta.to.shared.u64 t, %1; cvt.u32.u64 %0, t; }" : "=r"(a) : "l"(p));
    return a;
}
#define SWZ(off) ((off) ^ (((off) >> 3) & 0x70))

__device__ __forceinline__ void ldsm_x4(uint32_t* r, uint32_t addr) {
    asm volatile("ldmatrix.sync.aligned.m8n8.x4.shared.b16 {%0,%1,%2,%3}, [%4];"
                 : "=r"(r[0]), "=r"(r[1]), "=r"(r[2]), "=r"(r[3]) : "r"(addr));
}
__device__ __forceinline__ void ldsm_x2(uint32_t* r, uint32_t addr) {
    asm volatile("ldmatrix.sync.aligned.m8n8.x2.shared.b16 {%0,%1}, [%2];"
                 : "=r"(r[0]), "=r"(r[1]) : "r"(addr));
}
__device__ __forceinline__ void mma_bf16(float* c, const uint32_t* a, const uint32_t* b) {
    asm volatile("mma.sync.aligned.m16n8k16.row.col.f32.bf16.bf16.f32 "
                 "{%0,%1,%2,%3}, {%4,%5,%6,%7}, {%8,%9}, {%0,%1,%2,%3};"
                 : "+f"(c[0]), "+f"(c[1]), "+f"(c[2]), "+f"(c[3])
                 : "r"(a[0]), "r"(a[1]), "r"(a[2]), "r"(a[3]), "r"(b[0]), "r"(b[1]));
}

// Scratch (static device arrays — no allocations).
__device__ unsigned long long g_bar = 0ULL;              // monotonic grid barrier
__device__ double g_colsum[MAX_ITERS * NEXP];            // per-iteration column sums

__device__ __forceinline__ void grid_barrier()
{
    __syncthreads();
    if (threadIdx.x == 0) {
        __threadfence();
        unsigned long long my = atomicAdd(&g_bar, 1ULL);
        unsigned long long target = (my / GRIDB + 1ULL) * GRIDB;
        for (;;) {
            unsigned long long cur;
            asm volatile("ld.global.acquire.gpu.u64 %0, [%1];" : "=l"(cur) : "l"(&g_bar));
            if (cur >= target) break;
        }
    }
    __syncthreads();
}

__device__ __forceinline__ double warp_tree_add64(double s)
{
#pragma unroll
    for (int off = 16; off; off >>= 1)
        s += __shfl_xor_sync(0xffffffffu, s, off);
    return s;
}

// split 8 f32 -> 3x8 bf16, store 16B segments into the three tiles
__device__ __forceinline__ void split_store(char* dsm, int b1, int b2, int b3,
                                            uint32_t sw, float4 v0, float4 v1)
{
    float f[8] = {v0.x, v0.y, v0.z, v0.w, v1.x, v1.y, v1.z, v1.w};
    unsigned short h1[8], h2[8], h3[8];
#pragma unroll
    for (int i = 0; i < 8; i++) {
        float a = f[i];
        __nv_bfloat16 x1 = __float2bfloat16_rn(a);
        float r1 = a - __bfloat162float(x1);           // exact
        __nv_bfloat16 x2 = __float2bfloat16_rn(r1);
        float r2 = r1 - __bfloat162float(x2);          // exact
        __nv_bfloat16 x3 = __float2bfloat16_rn(r2);
        h1[i] = __bfloat16_as_ushort(x1);
        h2[i] = __bfloat16_as_ushort(x2);
        h3[i] = __bfloat16_as_ushort(x3);
    }
    uint4 q;
    q.x = h1[0] | ((uint32_t)h1[1] << 16); q.y = h1[2] | ((uint32_t)h1[3] << 16);
    q.z = h1[4] | ((uint32_t)h1[5] << 16); q.w = h1[6] | ((uint32_t)h1[7] << 16);
    *(uint4*)(dsm + b1 + sw) = q;
    q.x = h2[0] | ((uint32_t)h2[1] << 16); q.y = h2[2] | ((uint32_t)h2[3] << 16);
    q.z = h2[4] | ((uint32_t)h2[5] << 16); q.w = h2[6] | ((uint32_t)h2[7] << 16);
    *(uint4*)(dsm + b2 + sw) = q;
    q.x = h3[0] | ((uint32_t)h3[1] << 16); q.y = h3[2] | ((uint32_t)h3[3] << 16);
    q.z = h3[4] | ((uint32_t)h3[5] << 16); q.w = h3[6] | ((uint32_t)h3[7] << 16);
    *(uint4*)(dsm + b3 + sw) = q;
}

// ---------------------------------------------------------------------------
__global__ void __launch_bounds__(TPB, 1)
fused_router_kernel(const float* __restrict__ X, const float* __restrict__ W,
                    float* __restrict__ out, int out_size)
{
    extern __shared__ char dsm[];
    __shared__ float  warp_part[NW][NEXP];
    __shared__ double d1d[NEXP], d1pd[NEXP];
    __shared__ float  d1f[NEXP];
    __shared__ double s_err;

    const int tid  = threadIdx.x;
    const int bid  = blockIdx.x;
    const int lane = tid & 31;
    const int w    = tid >> 5;
    const int tok0 = bid * TOKB;
    const uint32_t smb = smem_u32(dsm);
    float* Cs = (float*)(dsm + SM_CS);

    // zero this launch's colsum slice
    for (int i = bid * TPB + tid; i < MAX_ITERS * NEXP; i += GRIDB * TPB)
        g_colsum[i] = 0.0;

    // ---------------- phase A: split-bf16 HMMA GEMM + exp ------------------
    // staging maps (identical to R7): A 1024 segs of 16B, threads own tid & tid+512
    const int as0 = tid, as1 = tid + 512;
    const int ar0 = as0 >> 3, ac0 = (as0 & 7) * 8;
    const int ar1 = as1 >> 3, ac1 = (as1 & 7) * 8;
    const uint32_t asw0 = SWZ((uint32_t)(ar0 * 128 + ac0 * 2));
    const uint32_t asw1 = SWZ((uint32_t)(ar1 * 128 + ac1 * 2));
    const int wr = tid >> 3, wc = (tid & 7) * 8;       // W: 512 segs
    const uint32_t wsw = SWZ((uint32_t)(wr * 128 + wc * 2));

    float4 ax0a, ax0b, ax1a, ax1b, wxa, wxb;
    {
        const float* pa0 = X + (size_t)(tok0 + ar0) * HID + ac0;
        const float* pa1 = X + (size_t)(tok0 + ar1) * HID + ac1;
        const float* pw  = W + (size_t)wr * HID + wc;
        ax0a = *(const float4*)pa0;  ax0b = *(const float4*)(pa0 + 4);
        ax1a = *(const float4*)pa1;  ax1b = *(const float4*)(pa1 + 4);
        wxa  = *(const float4*)pw;   wxb  = *(const float4*)(pw + 4);
    }

    // warp tile: M=16 rows at mrow0, N=32 cols at ncol0
    const int mrow0 = (w >> 1) * 16;
    const int ncol0 = (w & 1) * 32;
    // ldmatrix per-lane address components (swizzle decomposed:
    // addr = row*128 + (kbyte ^ ((row&7)<<4)) )
    const int arow  = mrow0 + (lane & 15);
    const uint32_t aconst = (uint32_t)(arow * 128);
    const uint32_t amask  = (uint32_t)((arow & 7) << 4);
    const uint32_t akoff  = (uint32_t)((lane >> 4) * 16);
    uint32_t bconst[4];
#pragma unroll
    for (int j = 0; j < 4; j++)
        bconst[j] = (uint32_t)((ncol0 + j * 8 + (lane & 7)) * 128);
    const uint32_t bmask = (uint32_t)((lane & 7) << 4);
    const uint32_t bkoff = (uint32_t)(((lane >> 3) & 1) * 16);

    const int SA[3] = {SM_A1, SM_A2, SM_A3};
    const int SB[3] = {SM_B1, SM_B2, SM_B3};
    // pair order smallest-magnitude first: a1b3, a2b2, a3b1, a2b1, a1b2, a1b1
    const int PAI[6] = {0, 1, 2, 1, 0, 0};
    const int PBI[6] = {2, 1, 0, 0, 1, 0};

    float hi[4][4];
#pragma unroll
    for (int j = 0; j < 4; j++)
#pragma unroll
        for (int q = 0; q < 4; q++) hi[j][q] = 0.f;

    for (int c = 0; c < NCHUNK; c++) {
        split_store(dsm, SM_A1, SM_A2, SM_A3, asw0, ax0a, ax0b);
        split_store(dsm, SM_A1, SM_A2, SM_A3, asw1, ax1a, ax1b);
        split_store(dsm, SM_B1, SM_B2, SM_B3, wsw,  wxa,  wxb);
        __syncthreads();

        if (c + 1 < NCHUNK) {   // prefetch next chunk (overlaps compute)
            int k0 = (c + 1) * BKC;
            const float* pa0 = X + (size_t)(tok0 + ar0) * HID + k0 + ac0;
            const float* pa1 = X + (size_t)(tok0 + ar1) * HID + k0 + ac1;
            const float* pw  = W + (size_t)wr * HID + k0 + wc;
            ax0a = *(const float4*)pa0;  ax0b = *(const float4*)(pa0 + 4);
            ax1a = *(const float4*)pa1;  ax1b = *(const float4*)(pa1 + 4);
            wxa  = *(const float4*)pw;   wxb  = *(const float4*)(pw + 4);
        }

        float accf[4][4];
#pragma unroll
        for (int j = 0; j < 4; j++)
#pragma unroll
            for (int q = 0; q < 4; q++) accf[j][q] = 0.f;

#pragma unroll
        for (int ks = 0; ks < 4; ks++) {
            uint32_t kb_a = (uint32_t)(ks * 32) + akoff;
            uint32_t kb_b = (uint32_t)(ks * 32) + bkoff;
            uint32_t afr[3][4], bfr[3][4][2];
#pragma unroll
            for (int s = 0; s < 3; s++)
                ldsm_x4(afr[s], smb + SA[s] + aconst + (kb_a ^ amask));
#pragma unroll
            for (int s = 0; s < 3; s++)
#pragma unroll
                for (int j = 0; j < 4; j++)
                    ldsm_x2(bfr[s][j], smb + SB[s] + bconst[j] + (kb_b ^ bmask));
#pragma unroll
            for (int p = 0; p < 6; p++)
#pragma unroll
                for (int j = 0; j < 4; j++)
                    mma_bf16(accf[j], afr[PAI[p]], bfr[PBI[p]][j]);
        }
#pragma unroll
        for (int j = 0; j < 4; j++)
#pragma unroll
            for (int q = 0; q < 4; q++) hi[j][q] += accf[j][q];
        __syncthreads();   // all smem reads done before next store / Cs overlay
    }

    // epilogue: exp(logits) into Cs (aliases A1/A2 region)
    {
        int r0 = mrow0 + (lane >> 2);
        int cbase = ncol0 + (lane & 3) * 2;
#pragma unroll
        for (int j = 0; j < 4; j++) {
            int cc = cbase + j * 8;
            float2 v0 = make_float2(__nv_expf(hi[j][0]), __nv_expf(hi[j][1]));
            float2 v1 = make_float2(__nv_expf(hi[j][2]), __nv_expf(hi[j][3]));
            *(float2*)&Cs[r0 * NEXP + cc]       = v0;
            *(float2*)&Cs[(r0 + 8) * NEXP + cc] = v1;
        }
    }
    if (tid < NEXP) { d1d[tid] = 1.0; d1pd[tid] = 1.0; d1f[tid] = 1.f; }
    grid_barrier();   // Cs ready; colsum zeros globally visible

    // ---------------- phase B: Sinkhorn iterations (as R6) ------------------
    const float  INVN0F = 1.0f / (float)NTOK;
    const float  EPSF   = 1e-8f;
    const double INVN1D = 1.0 / (double)NEXP;
    const double EPSD   = (double)1e-8f;

    for (int it = 0; it < MAX_ITERS; it++) {
        float d1a = d1f[lane];
        float d1c = d1f[lane + 32];
        float p0 = 0.f, p1 = 0.f;
        for (int t = w; t < TOKB; t += NW) {
            float c0 = Cs[t * NEXP + lane];
            float c1 = Cs[t * NEXP + lane + 32];
            float s  = fmaf(d1a, c0, d1c * c1);
#pragma unroll
            for (int off = 16; off; off >>= 1)
                s += __shfl_xor_sync(0xffffffffu, s, off);
            float d0 = frcp_approx(s + EPSF) * INVN0F;
            p0 = fmaf(d0, c0, p0);
            p1 = fmaf(d0, c1, p1);
        }
        warp_part[w][lane]      = p0;
        warp_part[w][lane + 32] = p1;
        __syncthreads();
        if (tid < NEXP) {
            double sum = 0.0;
#pragma unroll
            for (int ww = 0; ww < NW; ww++) sum += (double)warp_part[ww][tid];
            atomicAdd(&g_colsum[it * NEXP + tid], sum);
        }
        grid_barrier();

        if (w == 0) {
            double cs0 = g_colsum[it * NEXP + lane];
            double cs1 = g_colsum[it * NEXP + lane + 32];
            double v0  = INVN1D / (cs0 + EPSD);
            double v1  = INVN1D / (cs1 + EPSD);
            double o0  = d1d[lane];
            double o1  = d1d[lane + 32];
            double s   = warp_tree_add64(fabs(o0 - v0) + fabs(o1 - v1));
            d1pd[lane]      = o0;  d1pd[lane + 32] = o1;
            d1d[lane]       = v0;  d1d[lane + 32]  = v1;
            d1f[lane]       = (float)v0;
            d1f[lane + 32]  = (float)v1;
            if (lane == 0) s_err = s * INVN1D;
        }
        __syncthreads();
        if (s_err <= SINK_TOL) break;
    }

    // ---------------- phase C: top-2 (fp64) + softmax-gather ----------------
    const double INVN0D = 1.0 / (double)NTOK;
    double d1a = d1d[lane],  d1c = d1d[lane + 32];
    double dpa = d1pd[lane], dpc = d1pd[lane + 32];
    for (int t = w; t < TOKB; t += NW) {
        double c0 = (double)Cs[t * NEXP + lane];
        double c1 = (double)Cs[t * NEXP + lane + 32];
        double sr = warp_tree_add64(dpa * c0 + dpc * c1);
        double rs = warp_tree_add64(c0 + c1);
        double d0 = INVN0D / (sr + EPSD);
        double v0 = (d1a * c0) * d0;
        double v1 = (d1c * c1) * d0;

        double mv; int mi;
        if (v0 >= v1) { mv = v0; mi = lane; } else { mv = v1; mi = lane + 32; }
#pragma unroll
        for (int off = 16; off; off >>= 1) {
            double ov = __shfl_xor_sync(0xffffffffu, mv, off);
            int    oi = __shfl_xor_sync(0xffffffffu, mi, off);
            if (ov > mv || (ov == mv && oi < mi)) { mv = ov; mi = oi; }
        }
        double u0 = (lane      == mi) ? -1e308 : v0;
        double u1 = (lane + 32 == mi) ? -1e308 : v1;
        double mv2; int mi2;
        if (u0 >= u1) { mv2 = u0; mi2 = lane; } else { mv2 = u1; mi2 = lane + 32; }
#pragma unroll
        for (int off = 16; off; off >>= 1) {
            double ov = __shfl_xor_sync(0xffffffffu, mv2, off);
            int    oi = __shfl_xor_sync(0xffffffffu, mi2, off);
            if (ov > mv2 || (ov == mv2 && oi < mi2)) { mv2 = ov; mi2 = oi; }
        }

        if (lane == 0) {
            int tg = tok0 + t;
            float s0 = (float)((double)Cs[t * NEXP + mi]  / rs);
            float s1 = (float)((double)Cs[t * NEXP + mi2] / rs);
            if (out_size >= 4 * NTOK) {
                out[(size_t)tg * 2 + 0] = s0;
                out[(size_t)tg * 2 + 1] = s1;
                out[(size_t)2 * NTOK + tg * 2 + 0] = (float)mi;
                out[(size_t)2 * NTOK + tg * 2 + 1] = (float)mi2;
            } else {
                out[(size_t)tg * 2 + 0] = s0;
                out[(size_t)tg * 2 + 1] = s1;
            }
        }
    }
}

// ---------------------------------------------------------------------------
extern "C" void kernel_launch(void* const* d_in, const int* in_sizes, int n_in,
                              void* d_out, int out_size)
{
    const float* X = (const float*)d_in[0];
    const float* W = (const float*)d_in[1];
    if (n_in >= 2 && in_sizes[0] == NEXP * HID) {   // defensive input-order check
        X = (const float*)d_in[1];
        W = (const float*)d_in[0];
    }
    cudaFuncSetAttribute(fused_router_kernel,
                         cudaFuncAttributeMaxDynamicSharedMemorySize, DSM_TOTAL);
    fused_router_kernel<<<GRIDB, TPB, DSM_TOTAL>>>(X, W, (float*)d_out, out_size);
}

// round 9
// speedup vs baseline: 1.5738x; 1.0607x over previous
#include <cuda_runtime.h>
#include <cuda_bf16.h>
#include <cstdint>

#define HID   2048
#define NEXP  64
#define NTOK  16384
#define SINK_TOL 1e-4
#define MAX_ITERS 512
#define GRIDB 128
#define TPB   512
#define NW    16
#define TOKB  128          // 16384 = 128 * 128 exactly
#define BKC   64           // k-chunk (elems) -> 128 B bf16 rows (SW128 atom)
#define NCHUNK (HID / BKC) // 32

// per-buffer tile offsets (bytes); buffer = 72 KB, two buffers
#define TILE_A 16384       // 128 rows x 128 B
#define TILE_B 8192        //  64 rows x 128 B
#define OF_A1  0
#define OF_A2  16384
#define OF_A3  32768
#define OF_B1  49152
#define OF_B2  57344
#define OF_B3  65536
#define BUFSZ  73728
#define DSM_TOTAL (2 * BUFSZ)   // 147456 B dynamic smem

extern "C" __device__ float __nv_expf(float);

__device__ __forceinline__ float frcp_approx(float x) {
    float r; asm("rcp.approx.f32 %0,%1;" : "=f"(r) : "f"(x)); return r;
}
__device__ __forceinline__ uint32_t smem_u32(const void* p) {
    uint32_t a;
    asm("{ .reg .u64 t; cvta.to.shared.u64 t, %1; cvt.u32.u64 %0, t; }" : "=r"(a) : "l"(p));
    return a;
}
#define SWZ(off) ((off) ^ (((off) >> 3) & 0x70))

__device__ __forceinline__ void ldsm_x4(uint32_t* r, uint32_t addr) {
    asm volatile("ldmatrix.sync.aligned.m8n8.x4.shared.b16 {%0,%1,%2,%3}, [%4];"
                 : "=r"(r[0]), "=r"(r[1]), "=r"(r[2]), "=r"(r[3]) : "r"(addr));
}
__device__ __forceinline__ void ldsm_x2(uint32_t* r, uint32_t addr) {
    asm volatile("ldmatrix.sync.aligned.m8n8.x2.shared.b16 {%0,%1}, [%2];"
                 : "=r"(r[0]), "=r"(r[1]) : "r"(addr));
}
__device__ __forceinline__ void mma_bf16(float* c, const uint32_t* a, const uint32_t* b) {
    asm volatile("mma.sync.aligned.m16n8k16.row.col.f32.bf16.bf16.f32 "
                 "{%0,%1,%2,%3}, {%4,%5,%6,%7}, {%8,%9}, {%0,%1,%2,%3};"
                 : "+f"(c[0]), "+f"(c[1]), "+f"(c[2]), "+f"(c[3])
                 : "r"(a[0]), "r"(a[1]), "r"(a[2]), "r"(a[3]), "r"(b[0]), "r"(b[1]));
}

// Scratch (static device arrays — no allocations).
__device__ unsigned long long g_bar = 0ULL;              // monotonic grid barrier
__device__ double g_colsum[MAX_ITERS * NEXP];            // per-iteration column sums

__device__ __forceinline__ void grid_barrier()
{
    __syncthreads();
    if (threadIdx.x == 0) {
        __threadfence();
        unsigned long long my = atomicAdd(&g_bar, 1ULL);
        unsigned long long target = (my / GRIDB + 1ULL) * GRIDB;
        for (;;) {
            unsigned long long cur;
            asm volatile("ld.global.acquire.gpu.u64 %0, [%1];" : "=l"(cur) : "l"(&g_bar));
            if (cur >= target) break;
        }
    }
    __syncthreads();
}

__device__ __forceinline__ double warp_tree_add64(double s)
{
#pragma unroll
    for (int off = 16; off; off >>= 1)
        s += __shfl_xor_sync(0xffffffffu, s, off);
    return s;
}

// split 8 f32 -> 3x8 bf16, store 16B segments into three tiles (same as R8)
__device__ __forceinline__ void split_store(char* base, uint32_t sw,
                                            float4 v0, float4 v1)
{
    float f[8] = {v0.x, v0.y, v0.z, v0.w, v1.x, v1.y, v1.z, v1.w};
    unsigned short h1[8], h2[8], h3[8];
#pragma unroll
    for (int i = 0; i < 8; i++) {
        float a = f[i];
        __nv_bfloat16 x1 = __float2bfloat16_rn(a);
        float r1 = a - __bfloat162float(x1);           // exact
        __nv_bfloat16 x2 = __float2bfloat16_rn(r1);
        float r2 = r1 - __bfloat162float(x2);          // exact
        __nv_bfloat16 x3 = __float2bfloat16_rn(r2);
        h1[i] = __bfloat16_as_ushort(x1);
        h2[i] = __bfloat16_as_ushort(x2);
        h3[i] = __bfloat16_as_ushort(x3);
    }
    uint4 q;
    q.x = h1[0] | ((uint32_t)h1[1] << 16); q.y = h1[2] | ((uint32_t)h1[3] << 16);
    q.z = h1[4] | ((uint32_t)h1[5] << 16); q.w = h1[6] | ((uint32_t)h1[7] << 16);
    *(uint4*)(base + sw) = q;                           // split 1 tile
    q.x = h2[0] | ((uint32_t)h2[1] << 16); q.y = h2[2] | ((uint32_t)h2[3] << 16);
    q.z = h2[4] | ((uint32_t)h2[5] << 16); q.w = h2[6] | ((uint32_t)h2[7] << 16);
    *(uint4*)(base + 16384 + sw) = q;                   // split 2 tile (A spacing)
    q.x = h3[0] | ((uint32_t)h3[1] << 16); q.y = h3[2] | ((uint32_t)h3[3] << 16);
    q.z = h3[4] | ((uint32_t)h3[5] << 16); q.w = h3[6] | ((uint32_t)h3[7] << 16);
    *(uint4*)(base + 32768 + sw) = q;                   // split 3 tile
}
// B variant: tiles spaced 8192 B
__device__ __forceinline__ void split_storeB(char* base, uint32_t sw,
                                             float4 v0, float4 v1)
{
    float f[8] = {v0.x, v0.y, v0.z, v0.w, v1.x, v1.y, v1.z, v1.w};
    unsigned short h1[8], h2[8], h3[8];
#pragma unroll
    for (int i = 0; i < 8; i++) {
        float a = f[i];
        __nv_bfloat16 x1 = __float2bfloat16_rn(a);
        float r1 = a - __bfloat162float(x1);
        __nv_bfloat16 x2 = __float2bfloat16_rn(r1);
        float r2 = r1 - __bfloat162float(x2);
        __nv_bfloat16 x3 = __float2bfloat16_rn(r2);
        h1[i] = __bfloat16_as_ushort(x1);
        h2[i] = __bfloat16_as_ushort(x2);
        h3[i] = __bfloat16_as_ushort(x3);
    }
    uint4 q;
    q.x = h1[0] | ((uint32_t)h1[1] << 16); q.y = h1[2] | ((uint32_t)h1[3] << 16);
    q.z = h1[4] | ((uint32_t)h1[5] << 16); q.w = h1[6] | ((uint32_t)h1[7] << 16);
    *(uint4*)(base + sw) = q;
    q.x = h2[0] | ((uint32_t)h2[1] << 16); q.y = h2[2] | ((uint32_t)h2[3] << 16);
    q.z = h2[4] | ((uint32_t)h2[5] << 16); q.w = h2[6] | ((uint32_t)h2[7] << 16);
    *(uint4*)(base + 8192 + sw) = q;
    q.x = h3[0] | ((uint32_t)h3[1] << 16); q.y = h3[2] | ((uint32_t)h3[3] << 16);
    q.z = h3[4] | ((uint32_t)h3[5] << 16); q.w = h3[6] | ((uint32_t)h3[7] << 16);
    *(uint4*)(base + 16384 + sw) = q;
}

// ---------------------------------------------------------------------------
__global__ void __launch_bounds__(TPB, 1)
fused_router_kernel(const float* __restrict__ X, const float* __restrict__ W,
                    float* __restrict__ out, int out_size)
{
    extern __shared__ char dsm[];
    __shared__ float  warp_part[NW][NEXP];
    __shared__ double d1d[NEXP], d1pd[NEXP];
    __shared__ float  d1f[NEXP];
    __shared__ double s_err;

    const int tid  = threadIdx.x;
    const int bid  = blockIdx.x;
    const int lane = tid & 31;
    const int w    = tid >> 5;
    const int tok0 = bid * TOKB;
    const uint32_t smb = smem_u32(dsm);
    float* Cs = (float*)dsm;    // overlays buf0 after GEMM completes

    // zero this launch's colsum slice
    for (int i = bid * TPB + tid; i < MAX_ITERS * NEXP; i += GRIDB * TPB)
        g_colsum[i] = 0.0;

    // ================= phase A: producer/consumer split-bf16 HMMA ==========
    const bool producer = (w >= 8);
    // consumer tile coords
    const int mt = (w & 7) >> 1;          // m-tile 0..3 (32 rows each)
    const int nh = w & 1;                 // n-half 0..1 (32 cols)

    // consumer ldsm address components
    uint32_t aconst[2], amask[2];
#pragma unroll
    for (int mi = 0; mi < 2; mi++) {
        int arow = mt * 32 + mi * 16 + (lane & 15);
        aconst[mi] = (uint32_t)(arow * 128);
        amask[mi]  = (uint32_t)((arow & 7) << 4);
    }
    const uint32_t akoff = (uint32_t)((lane >> 4) * 16);
    uint32_t bconst[4];
#pragma unroll
    for (int j = 0; j < 4; j++)
        bconst[j] = (uint32_t)((nh * 32 + j * 8 + (lane & 7)) * 128);
    const uint32_t bmask = (uint32_t)((lane & 7) << 4);
    const uint32_t bkoff = (uint32_t)(((lane >> 3) & 1) * 16);

    const uint32_t SA[3] = {OF_A1, OF_A2, OF_A3};
    const uint32_t SB[3] = {OF_B1, OF_B2, OF_B3};
    const int PAI[6] = {0, 1, 2, 1, 0, 0};   // a1b3,a2b2,a3b1,a2b1,a1b2,a1b1
    const int PBI[6] = {2, 1, 0, 0, 1, 0};

    // producer maps: A 1024 segs (4/thread), B 512 segs (2/thread)
    const int ptid = tid & 255;
    uint32_t asw_p[4]; size_t aoff_p[4];
    uint32_t bsw_p[2]; size_t boff_p[2];
#pragma unroll
    for (int j = 0; j < 4; j++) {
        int seg = ptid + j * 256;
        int row = seg >> 3, kq = (seg & 7) * 8;
        asw_p[j]  = SWZ((uint32_t)(row * 128 + kq * 2));
        aoff_p[j] = (size_t)(tok0 + row) * HID + kq;
    }
#pragma unroll
    for (int j = 0; j < 2; j++) {
        int seg = ptid + j * 256;
        int row = seg >> 3, kq = (seg & 7) * 8;
        bsw_p[j]  = SWZ((uint32_t)(row * 128 + kq * 2));
        boff_p[j] = (size_t)row * HID + kq;
    }

    float4 av[4][2], bvv[2][2];
    if (producer) {   // prefetch chunk 0
#pragma unroll
        for (int j = 0; j < 4; j++) {
            av[j][0] = *(const float4*)(X + aoff_p[j]);
            av[j][1] = *(const float4*)(X + aoff_p[j] + 4);
        }
#pragma unroll
        for (int j = 0; j < 2; j++) {
            bvv[j][0] = *(const float4*)(W + boff_p[j]);
            bvv[j][1] = *(const float4*)(W + boff_p[j] + 4);
        }
    }

    float hi[2][4][4];
#pragma unroll
    for (int mi = 0; mi < 2; mi++)
#pragma unroll
        for (int j = 0; j < 4; j++)
#pragma unroll
            for (int q = 0; q < 4; q++) hi[mi][j][q] = 0.f;

    for (int it = 0; it <= NCHUNK; it++) {
        if (producer) {
            if (it < NCHUNK) {
                char* base = dsm + (it & 1) * BUFSZ;
#pragma unroll
                for (int j = 0; j < 4; j++)
                    split_store(base + OF_A1, asw_p[j], av[j][0], av[j][1]);
#pragma unroll
                for (int j = 0; j < 2; j++)
                    split_storeB(base + OF_B1, bsw_p[j], bvv[j][0], bvv[j][1]);
                if (it + 1 < NCHUNK) {
                    int k0 = (it + 1) * BKC;
#pragma unroll
                    for (int j = 0; j < 4; j++) {
                        av[j][0] = *(const float4*)(X + aoff_p[j] + k0);
                        av[j][1] = *(const float4*)(X + aoff_p[j] + k0 + 4);
                    }
#pragma unroll
                    for (int j = 0; j < 2; j++) {
                        bvv[j][0] = *(const float4*)(W + boff_p[j] + k0);
                        bvv[j][1] = *(const float4*)(W + boff_p[j] + k0 + 4);
                    }
                }
            }
        } else if (it >= 1) {
            const uint32_t bb = smb + (uint32_t)(((it - 1) & 1) * BUFSZ);
            float accf[2][4][4];
#pragma unroll
            for (int mi = 0; mi < 2; mi++)
#pragma unroll
                for (int j = 0; j < 4; j++)
#pragma unroll
                    for (int q = 0; q < 4; q++) accf[mi][j][q] = 0.f;
#pragma unroll
            for (int ks = 0; ks < 4; ks++) {
                uint32_t kb_a = (uint32_t)(ks * 32) + akoff;
                uint32_t kb_b = (uint32_t)(ks * 32) + bkoff;
                uint32_t afr[3][2][4];
#pragma unroll
                for (int s = 0; s < 3; s++)
#pragma unroll
                    for (int mi = 0; mi < 2; mi++)
                        ldsm_x4(afr[s][mi], bb + SA[s] + aconst[mi] + (kb_a ^ amask[mi]));
#pragma unroll
                for (int j = 0; j < 4; j++) {
                    uint32_t bfr[3][2];
#pragma unroll
                    for (int s = 0; s < 3; s++)
                        ldsm_x2(bfr[s], bb + SB[s] + bconst[j] + (kb_b ^ bmask));
#pragma unroll
                    for (int p = 0; p < 6; p++)
#pragma unroll
                        for (int mi = 0; mi < 2; mi++)
                            mma_bf16(accf[mi][j], afr[PAI[p]][mi], bfr[PBI[p]]);
                }
            }
#pragma unroll
            for (int mi = 0; mi < 2; mi++)
#pragma unroll
                for (int j = 0; j < 4; j++)
#pragma unroll
                    for (int q = 0; q < 4; q++) hi[mi][j][q] += accf[mi][j][q];
        }
        __syncthreads();
    }

    // epilogue: consumers write exp(logits) into Cs (overlays buf0)
    if (!producer) {
#pragma unroll
        for (int mi = 0; mi < 2; mi++) {
            int r0 = mt * 32 + mi * 16 + (lane >> 2);
#pragma unroll
            for (int j = 0; j < 4; j++) {
                int cc = nh * 32 + j * 8 + (lane & 3) * 2;
                float2 v0 = make_float2(__nv_expf(hi[mi][j][0]), __nv_expf(hi[mi][j][1]));
                float2 v1 = make_float2(__nv_expf(hi[mi][j][2]), __nv_expf(hi[mi][j][3]));
                *(float2*)&Cs[r0 * NEXP + cc]       = v0;
                *(float2*)&Cs[(r0 + 8) * NEXP + cc] = v1;
            }
        }
    }
    if (tid < NEXP) { d1d[tid] = 1.0; d1pd[tid] = 1.0; d1f[tid] = 1.f; }
    grid_barrier();   // Cs ready; colsum zeros globally visible

    // ================= phase B: Sinkhorn iterations (as R8) ================
    const float  INVN0F = 1.0f / (float)NTOK;
    const float  EPSF   = 1e-8f;
    const double INVN1D = 1.0 / (double)NEXP;
    const double EPSD   = (double)1e-8f;

    for (int it = 0; it < MAX_ITERS; it++) {
        float d1a = d1f[lane];
        float d1c = d1f[lane + 32];
        float p0 = 0.f, p1 = 0.f;
        for (int t = w; t < TOKB; t += NW) {
            float c0 = Cs[t * NEXP + lane];
            float c1 = Cs[t * NEXP + lane + 32];
            float s  = fmaf(d1a, c0, d1c * c1);
#pragma unroll
            for (int off = 16; off; off >>= 1)
                s += __shfl_xor_sync(0xffffffffu, s, off);
            float d0 = frcp_approx(s + EPSF) * INVN0F;
            p0 = fmaf(d0, c0, p0);
            p1 = fmaf(d0, c1, p1);
        }
        warp_part[w][lane]      = p0;
        warp_part[w][lane + 32] = p1;
        __syncthreads();
        if (tid < NEXP) {
            double sum = 0.0;
#pragma unroll
            for (int ww = 0; ww < NW; ww++) sum += (double)warp_part[ww][tid];
            atomicAdd(&g_colsum[it * NEXP + tid], sum);
        }
        grid_barrier();

        if (w == 0) {
            double cs0 = g_colsum[it * NEXP + lane];
            double cs1 = g_colsum[it * NEXP + lane + 32];
            double v0  = INVN1D / (cs0 + EPSD);
            double v1  = INVN1D / (cs1 + EPSD);
            double o0  = d1d[lane];
            double o1  = d1d[lane + 32];
            double s   = warp_tree_add64(fabs(o0 - v0) + fabs(o1 - v1));
            d1pd[lane]      = o0;  d1pd[lane + 32] = o1;
            d1d[lane]       = v0;  d1d[lane + 32]  = v1;
            d1f[lane]       = (float)v0;
            d1f[lane + 32]  = (float)v1;
            if (lane == 0) s_err = s * INVN1D;
        }
        __syncthreads();
        if (s_err <= SINK_TOL) break;
    }

    // ================= phase C: top-2 (fp64) + softmax-gather ==============
    const double INVN0D = 1.0 / (double)NTOK;
    double d1a = d1d[lane],  d1c = d1d[lane + 32];
    double dpa = d1pd[lane], dpc = d1pd[lane + 32];
    for (int t = w; t < TOKB; t += NW) {
        double c0 = (double)Cs[t * NEXP + lane];
        double c1 = (double)Cs[t * NEXP + lane + 32];
        double sr = warp_tree_add64(dpa * c0 + dpc * c1);
        double rs = warp_tree_add64(c0 + c1);
        double d0 = INVN0D / (sr + EPSD);
        double v0 = (d1a * c0) * d0;
        double v1 = (d1c * c1) * d0;

        double mv; int mi;
        if (v0 >= v1) { mv = v0; mi = lane; } else { mv = v1; mi = lane + 32; }
#pragma unroll
        for (int off = 16; off; off >>= 1) {
            double ov = __shfl_xor_sync(0xffffffffu, mv, off);
            int    oi = __shfl_xor_sync(0xffffffffu, mi, off);
            if (ov > mv || (ov == mv && oi < mi)) { mv = ov; mi = oi; }
        }
        double u0 = (lane      == mi) ? -1e308 : v0;
        double u1 = (lane + 32 == mi) ? -1e308 : v1;
        double mv2; int mi2;
        if (u0 >= u1) { mv2 = u0; mi2 = lane; } else { mv2 = u1; mi2 = lane + 32; }
#pragma unroll
        for (int off = 16; off; off >>= 1) {
            double ov = __shfl_xor_sync(0xffffffffu, mv2, off);
            int    oi = __shfl_xor_sync(0xffffffffu, mi2, off);
            if (ov > mv2 || (ov == mv2 && oi < mi2)) { mv2 = ov; mi2 = oi; }
        }

        if (lane == 0) {
            int tg = tok0 + t;
            float s0 = (float)((double)Cs[t * NEXP + mi]  / rs);
            float s1 = (float)((double)Cs[t * NEXP + mi2] / rs);
            if (out_size >= 4 * NTOK) {
                out[(size_t)tg * 2 + 0] = s0;
                out[(size_t)tg * 2 + 1] = s1;
                out[(size_t)2 * NTOK + tg * 2 + 0] = (float)mi;
                out[(size_t)2 * NTOK + tg * 2 + 1] = (float)mi2;
            } else {
                out[(size_t)tg * 2 + 0] = s0;
                out[(size_t)tg * 2 + 1] = s1;
            }
        }
    }
}

// ---------------------------------------------------------------------------
extern "C" void kernel_launch(void* const* d_in, const int* in_sizes, int n_in,
                              void* d_out, int out_size)
{
    const float* X = (const float*)d_in[0];
    const float* W = (const float*)d_in[1];
    if (n_in >= 2 && in_sizes[0] == NEXP * HID) {   // defensive input-order check
        X = (const float*)d_in[1];
        W = (const float*)d_in[0];
    }
    cudaFuncSetAttribute(fused_router_kernel,
                         cudaFuncAttributeMaxDynamicSharedMemorySize, DSM_TOTAL);
    fused_router_kernel<<<GRIDB, TPB, DSM_TOTAL>>>(X, W, (float*)d_out, out_size);
}

// round 10
// speedup vs baseline: 1.6066x; 1.0208x over previous
#include <cuda_runtime.h>
#include <cuda_bf16.h>
#include <cstdint>

#define HID   2048
#define NEXP  64
#define NTOK  16384
#define SINK_TOL 1e-4
#define MAX_ITERS 512
#define GRIDB 128
#define TPB   512
#define NW    16
#define TOKB  128          // 16384 = 128 * 128 exactly
#define BKC   64           // k-chunk (elems) -> 128 B bf16 rows (SW128 atom)
#define NCHUNK (HID / BKC) // 32
#define CSTRIDE 16         // colsum pad: 16 doubles = 128 B per expert column

// per-buffer tile offsets (bytes); buffer = 72 KB, two buffers
#define TILE_A 16384
#define TILE_B 8192
#define OF_A1  0
#define OF_A2  16384
#define OF_A3  32768
#define OF_B1  49152
#define OF_B2  57344
#define OF_B3  65536
#define BUFSZ  73728
#define DSM_TOTAL (2 * BUFSZ)   // 147456 B dynamic smem

extern "C" __device__ float __nv_expf(float);

__device__ __forceinline__ float frcp_approx(float x) {
    float r; asm("rcp.approx.f32 %0,%1;" : "=f"(r) : "f"(x)); return r;
}
__device__ __forceinline__ uint32_t smem_u32(const void* p) {
    uint32_t a;
    asm("{ .reg .u64 t; cvta.to.shared.u64 t, %1; cvt.u32.u64 %0, t; }" : "=r"(a) : "l"(p));
    return a;
}
#define SWZ(off) ((off) ^ (((off) >> 3) & 0x70))

__device__ __forceinline__ void ldsm_x4(uint32_t* r, uint32_t addr) {
    asm volatile("ldmatrix.sync.aligned.m8n8.x4.shared.b16 {%0,%1,%2,%3}, [%4];"
                 : "=r"(r[0]), "=r"(r[1]), "=r"(r[2]), "=r"(r[3]) : "r"(addr));
}
__device__ __forceinline__ void ldsm_x2(uint32_t* r, uint32_t addr) {
    asm volatile("ldmatrix.sync.aligned.m8n8.x2.shared.b16 {%0,%1}, [%2];"
                 : "=r"(r[0]), "=r"(r[1]) : "r"(addr));
}
__device__ __forceinline__ void mma_bf16(float* c, const uint32_t* a, const uint32_t* b) {
    asm volatile("mma.sync.aligned.m16n8k16.row.col.f32.bf16.bf16.f32 "
                 "{%0,%1,%2,%3}, {%4,%5,%6,%7}, {%8,%9}, {%0,%1,%2,%3};"
                 : "+f"(c[0]), "+f"(c[1]), "+f"(c[2]), "+f"(c[3])
                 : "r"(a[0]), "r"(a[1]), "r"(a[2]), "r"(a[3]), "r"(b[0]), "r"(b[1]));
}

// Scratch (static device arrays — no allocations).
__device__ unsigned long long g_bar = 0ULL;                      // grid barrier
__device__ double g_colsum[MAX_ITERS * NEXP * CSTRIDE];          // padded colsums, 4 MB

__device__ __forceinline__ void grid_barrier()
{
    __syncthreads();
    if (threadIdx.x == 0) {
        __threadfence();
        unsigned long long my = atomicAdd(&g_bar, 1ULL);
        unsigned long long target = (my / GRIDB + 1ULL) * GRIDB;
        for (;;) {
            unsigned long long cur;
            asm volatile("ld.global.acquire.gpu.u64 %0, [%1];" : "=l"(cur) : "l"(&g_bar));
            if (cur >= target) break;
        }
    }
    __syncthreads();
}

__device__ __forceinline__ double warp_tree_add64(double s)
{
#pragma unroll
    for (int off = 16; off; off >>= 1)
        s += __shfl_xor_sync(0xffffffffu, s, off);
    return s;
}

// split 8 f32 -> 3x8 bf16, store 16B segments into three tiles (A spacing 16 KB)
__device__ __forceinline__ void split_store(char* base, uint32_t sw,
                                            float4 v0, float4 v1)
{
    float f[8] = {v0.x, v0.y, v0.z, v0.w, v1.x, v1.y, v1.z, v1.w};
    unsigned short h1[8], h2[8], h3[8];
#pragma unroll
    for (int i = 0; i < 8; i++) {
        float a = f[i];
        __nv_bfloat16 x1 = __float2bfloat16_rn(a);
        float r1 = a - __bfloat162float(x1);           // exact
        __nv_bfloat16 x2 = __float2bfloat16_rn(r1);
        float r2 = r1 - __bfloat162float(x2);          // exact
        __nv_bfloat16 x3 = __float2bfloat16_rn(r2);
        h1[i] = __bfloat16_as_ushort(x1);
        h2[i] = __bfloat16_as_ushort(x2);
        h3[i] = __bfloat16_as_ushort(x3);
    }
    uint4 q;
    q.x = h1[0] | ((uint32_t)h1[1] << 16); q.y = h1[2] | ((uint32_t)h1[3] << 16);
    q.z = h1[4] | ((uint32_t)h1[5] << 16); q.w = h1[6] | ((uint32_t)h1[7] << 16);
    *(uint4*)(base + sw) = q;
    q.x = h2[0] | ((uint32_t)h2[1] << 16); q.y = h2[2] | ((uint32_t)h2[3] << 16);
    q.z = h2[4] | ((uint32_t)h2[5] << 16); q.w = h2[6] | ((uint32_t)h2[7] << 16);
    *(uint4*)(base + 16384 + sw) = q;
    q.x = h3[0] | ((uint32_t)h3[1] << 16); q.y = h3[2] | ((uint32_t)h3[3] << 16);
    q.z = h3[4] | ((uint32_t)h3[5] << 16); q.w = h3[6] | ((uint32_t)h3[7] << 16);
    *(uint4*)(base + 32768 + sw) = q;
}
// B variant: tiles spaced 8192 B
__device__ __forceinline__ void split_storeB(char* base, uint32_t sw,
                                             float4 v0, float4 v1)
{
    float f[8] = {v0.x, v0.y, v0.z, v0.w, v1.x, v1.y, v1.z, v1.w};
    unsigned short h1[8], h2[8], h3[8];
#pragma unroll
    for (int i = 0; i < 8; i++) {
        float a = f[i];
        __nv_bfloat16 x1 = __float2bfloat16_rn(a);
        float r1 = a - __bfloat162float(x1);
        __nv_bfloat16 x2 = __float2bfloat16_rn(r1);
        float r2 = r1 - __bfloat162float(x2);
        __nv_bfloat16 x3 = __float2bfloat16_rn(r2);
        h1[i] = __bfloat16_as_ushort(x1);
        h2[i] = __bfloat16_as_ushort(x2);
        h3[i] = __bfloat16_as_ushort(x3);
    }
    uint4 q;
    q.x = h1[0] | ((uint32_t)h1[1] << 16); q.y = h1[2] | ((uint32_t)h1[3] << 16);
    q.z = h1[4] | ((uint32_t)h1[5] << 16); q.w = h1[6] | ((uint32_t)h1[7] << 16);
    *(uint4*)(base + sw) = q;
    q.x = h2[0] | ((uint32_t)h2[1] << 16); q.y = h2[2] | ((uint32_t)h2[3] << 16);
    q.z = h2[4] | ((uint32_t)h2[5] << 16); q.w = h2[6] | ((uint32_t)h2[7] << 16);
    *(uint4*)(base + 8192 + sw) = q;
    q.x = h3[0] | ((uint32_t)h3[1] << 16); q.y = h3[2] | ((uint32_t)h3[3] << 16);
    q.z = h3[4] | ((uint32_t)h3[5] << 16); q.w = h3[6] | ((uint32_t)h3[7] << 16);
    *(uint4*)(base + 16384 + sw) = q;
}

// ---------------------------------------------------------------------------
__global__ void __launch_bounds__(TPB, 1)
fused_router_kernel(const float* __restrict__ X, const float* __restrict__ W,
                    float* __restrict__ out, int out_size)
{
    extern __shared__ char dsm[];
    __shared__ float  warp_part[NW][NEXP];
    __shared__ double d1d[NEXP], d1pd[NEXP];
    __shared__ float  d1f[NEXP];
    __shared__ double s_err;

    const int tid  = threadIdx.x;
    const int bid  = blockIdx.x;
    const int lane = tid & 31;
    const int w    = tid >> 5;
    const int tok0 = bid * TOKB;
    const uint32_t smb = smem_u32(dsm);
    float* Cs = (float*)dsm;    // overlays buf0 after GEMM completes

    // zero this launch's colsum slots (only the used, padded slots)
    for (int i = bid * TPB + tid; i < MAX_ITERS * NEXP; i += GRIDB * TPB)
        g_colsum[(size_t)i * CSTRIDE] = 0.0;

    // ================= phase A: producer/consumer split-bf16 HMMA ==========
    const bool producer = (w >= 8);
    const int mt = (w & 7) >> 1;          // m-tile 0..3 (32 rows each)
    const int nh = w & 1;                 // n-half 0..1 (32 cols)

    uint32_t aconst[2], amask[2];
#pragma unroll
    for (int mi = 0; mi < 2; mi++) {
        int arow = mt * 32 + mi * 16 + (lane & 15);
        aconst[mi] = (uint32_t)(arow * 128);
        amask[mi]  = (uint32_t)((arow & 7) << 4);
    }
    const uint32_t akoff = (uint32_t)((lane >> 4) * 16);
    uint32_t bconst[4];
#pragma unroll
    for (int j = 0; j < 4; j++)
        bconst[j] = (uint32_t)((nh * 32 + j * 8 + (lane & 7)) * 128);
    const uint32_t bmask = (uint32_t)((lane & 7) << 4);
    const uint32_t bkoff = (uint32_t)(((lane >> 3) & 1) * 16);

    const uint32_t SA[3] = {OF_A1, OF_A2, OF_A3};
    const uint32_t SB[3] = {OF_B1, OF_B2, OF_B3};
    const int PAI[6] = {0, 1, 2, 1, 0, 0};   // a1b3,a2b2,a3b1,a2b1,a1b2,a1b1
    const int PBI[6] = {2, 1, 0, 0, 1, 0};

    const int ptid = tid & 255;
    uint32_t asw_p[4]; size_t aoff_p[4];
    uint32_t bsw_p[2]; size_t boff_p[2];
#pragma unroll
    for (int j = 0; j < 4; j++) {
        int seg = ptid + j * 256;
        int row = seg >> 3, kq = (seg & 7) * 8;
        asw_p[j]  = SWZ((uint32_t)(row * 128 + kq * 2));
        aoff_p[j] = (size_t)(tok0 + row) * HID + kq;
    }
#pragma unroll
    for (int j = 0; j < 2; j++) {
        int seg = ptid + j * 256;
        int row = seg >> 3, kq = (seg & 7) * 8;
        bsw_p[j]  = SWZ((uint32_t)(row * 128 + kq * 2));
        boff_p[j] = (size_t)row * HID + kq;
    }

    float4 av[4][2], bvv[2][2];
    if (producer) {
#pragma unroll
        for (int j = 0; j < 4; j++) {
            av[j][0] = *(const float4*)(X + aoff_p[j]);
            av[j][1] = *(const float4*)(X + aoff_p[j] + 4);
        }
#pragma unroll
        for (int j = 0; j < 2; j++) {
            bvv[j][0] = *(const float4*)(W + boff_p[j]);
            bvv[j][1] = *(const float4*)(W + boff_p[j] + 4);
        }
    }

    float hi[2][4][4];
#pragma unroll
    for (int mi = 0; mi < 2; mi++)
#pragma unroll
        for (int j = 0; j < 4; j++)
#pragma unroll
            for (int q = 0; q < 4; q++) hi[mi][j][q] = 0.f;

    for (int it = 0; it <= NCHUNK; it++) {
        if (producer) {
            if (it < NCHUNK) {
                char* base = dsm + (it & 1) * BUFSZ;
#pragma unroll
                for (int j = 0; j < 4; j++)
                    split_store(base + OF_A1, asw_p[j], av[j][0], av[j][1]);
#pragma unroll
                for (int j = 0; j < 2; j++)
                    split_storeB(base + OF_B1, bsw_p[j], bvv[j][0], bvv[j][1]);
                if (it + 1 < NCHUNK) {
                    int k0 = (it + 1) * BKC;
#pragma unroll
                    for (int j = 0; j < 4; j++) {
                        av[j][0] = *(const float4*)(X + aoff_p[j] + k0);
                        av[j][1] = *(const float4*)(X + aoff_p[j] + k0 + 4);
                    }
#pragma unroll
                    for (int j = 0; j < 2; j++) {
                        bvv[j][0] = *(const float4*)(W + boff_p[j] + k0);
                        bvv[j][1] = *(const float4*)(W + boff_p[j] + k0 + 4);
                    }
                }
            }
        } else if (it >= 1) {
            const uint32_t bb = smb + (uint32_t)(((it - 1) & 1) * BUFSZ);
            float accf[2][4][4];
#pragma unroll
            for (int mi = 0; mi < 2; mi++)
#pragma unroll
                for (int j = 0; j < 4; j++)
#pragma unroll
                    for (int q = 0; q < 4; q++) accf[mi][j][q] = 0.f;
#pragma unroll
            for (int ks = 0; ks < 4; ks++) {
                uint32_t kb_a = (uint32_t)(ks * 32) + akoff;
                uint32_t kb_b = (uint32_t)(ks * 32) + bkoff;
                uint32_t afr[3][2][4];
#pragma unroll
                for (int s = 0; s < 3; s++)
#pragma unroll
                    for (int mi = 0; mi < 2; mi++)
                        ldsm_x4(afr[s][mi], bb + SA[s] + aconst[mi] + (kb_a ^ amask[mi]));
#pragma unroll
                for (int j = 0; j < 4; j++) {
                    uint32_t bfr[3][2];
#pragma unroll
                    for (int s = 0; s < 3; s++)
                        ldsm_x2(bfr[s], bb + SB[s] + bconst[j] + (kb_b ^ bmask));
#pragma unroll
                    for (int p = 0; p < 6; p++)
#pragma unroll
                        for (int mi = 0; mi < 2; mi++)
                            mma_bf16(accf[mi][j], afr[PAI[p]][mi], bfr[PBI[p]]);
                }
            }
#pragma unroll
            for (int mi = 0; mi < 2; mi++)
#pragma unroll
                for (int j = 0; j < 4; j++)
#pragma unroll
                    for (int q = 0; q < 4; q++) hi[mi][j][q] += accf[mi][j][q];
        }
        __syncthreads();
    }

    // epilogue: consumers write exp(logits) into Cs (overlays buf0)
    if (!producer) {
#pragma unroll
        for (int mi = 0; mi < 2; mi++) {
            int r0 = mt * 32 + mi * 16 + (lane >> 2);
#pragma unroll
            for (int j = 0; j < 4; j++) {
                int cc = nh * 32 + j * 8 + (lane & 3) * 2;
                float2 v0 = make_float2(__nv_expf(hi[mi][j][0]), __nv_expf(hi[mi][j][1]));
                float2 v1 = make_float2(__nv_expf(hi[mi][j][2]), __nv_expf(hi[mi][j][3]));
                *(float2*)&Cs[r0 * NEXP + cc]       = v0;
                *(float2*)&Cs[(r0 + 8) * NEXP + cc] = v1;
            }
        }
    }
    if (tid < NEXP) { d1d[tid] = 1.0; d1pd[tid] = 1.0; d1f[tid] = 1.f; }
    grid_barrier();   // Cs ready; colsum zeros globally visible

    // ================= phase B: Sinkhorn iterations ========================
    const float  INVN0F = 1.0f / (float)NTOK;
    const float  EPSF   = 1e-8f;
    const double INVN1D = 1.0 / (double)NEXP;
    const double EPSD   = (double)1e-8f;
    const int    esl    = (tid < NEXP) ? ((tid + (bid << 2)) & 63) : 0;  // staggered expert

    for (int it = 0; it < MAX_ITERS; it++) {
        float d1a = d1f[lane];
        float d1c = d1f[lane + 32];
        float p0 = 0.f, p1 = 0.f;
        // 4-way interleaved row pass; p0/p1 accumulate in the ORIGINAL
        // sequential token order (w, w+16, w+32, ...) -> bitwise identical.
#pragma unroll
        for (int g = 0; g < 2; g++) {
            int tb = w + g * 64;
            float c0[4], c1[4], s[4];
#pragma unroll
            for (int q = 0; q < 4; q++) {
                int t = tb + q * NW;
                c0[q] = Cs[t * NEXP + lane];
                c1[q] = Cs[t * NEXP + lane + 32];
                s[q]  = fmaf(d1a, c0[q], d1c * c1[q]);
            }
#pragma unroll
            for (int off = 16; off; off >>= 1)
#pragma unroll
                for (int q = 0; q < 4; q++)
                    s[q] += __shfl_xor_sync(0xffffffffu, s[q], off);
#pragma unroll
            for (int q = 0; q < 4; q++) {
                float d0 = frcp_approx(s[q] + EPSF) * INVN0F;
                p0 = fmaf(d0, c0[q], p0);
                p1 = fmaf(d0, c1[q], p1);
            }
        }
        warp_part[w][lane]      = p0;
        warp_part[w][lane + 32] = p1;
        __syncthreads();
        if (tid < NEXP) {
            double sum = 0.0;
#pragma unroll
            for (int ww = 0; ww < NW; ww++) sum += (double)warp_part[ww][esl];
            atomicAdd(&g_colsum[((size_t)it * NEXP + esl) * CSTRIDE], sum);
        }
        grid_barrier();

        if (w == 0) {
            double cs0 = g_colsum[((size_t)it * NEXP + lane) * CSTRIDE];
            double cs1 = g_colsum[((size_t)it * NEXP + lane + 32) * CSTRIDE];
            double v0  = INVN1D / (cs0 + EPSD);
            double v1  = INVN1D / (cs1 + EPSD);
            double o0  = d1d[lane];
            double o1  = d1d[lane + 32];
            double s   = warp_tree_add64(fabs(o0 - v0) + fabs(o1 - v1));
            d1pd[lane]      = o0;  d1pd[lane + 32] = o1;
            d1d[lane]       = v0;  d1d[lane + 32]  = v1;
            d1f[lane]       = (float)v0;
            d1f[lane + 32]  = (float)v1;
            if (lane == 0) s_err = s * INVN1D;
        }
        __syncthreads();
        if (s_err <= SINK_TOL) break;
    }

    // ================= phase C: top-2 (fp64) + softmax-gather ==============
    const double INVN0D = 1.0 / (double)NTOK;
    double d1a = d1d[lane],  d1c = d1d[lane + 32];
    double dpa = d1pd[lane], dpc = d1pd[lane + 32];
    for (int t = w; t < TOKB; t += NW) {
        double c0 = (double)Cs[t * NEXP + lane];
        double c1 = (double)Cs[t * NEXP + lane + 32];
        double sr = warp_tree_add64(dpa * c0 + dpc * c1);
        double rs = warp_tree_add64(c0 + c1);
        double d0 = INVN0D / (sr + EPSD);
        double v0 = (d1a * c0) * d0;
        double v1 = (d1c * c1) * d0;

        double mv; int mi;
        if (v0 >= v1) { mv = v0; mi = lane; } else { mv = v1; mi = lane + 32; }
#pragma unroll
        for (int off = 16; off; off >>= 1) {
            double ov = __shfl_xor_sync(0xffffffffu, mv, off);
            int    oi = __shfl_xor_sync(0xffffffffu, mi, off);
            if (ov > mv || (ov == mv && oi < mi)) { mv = ov; mi = oi; }
        }
        double u0 = (lane      == mi) ? -1e308 : v0;
        double u1 = (lane + 32 == mi) ? -1e308 : v1;
        double mv2; int mi2;
        if (u0 >= u1) { mv2 = u0; mi2 = lane; } else { mv2 = u1; mi2 = lane + 32; }
#pragma unroll
        for (int off = 16; off; off >>= 1) {
            double ov = __shfl_xor_sync(0xffffffffu, mv2, off);
            int    oi = __shfl_xor_sync(0xffffffffu, mi2, off);
            if (ov > mv2 || (ov == mv2 && oi < mi2)) { mv2 = ov; mi2 = oi; }
        }

        if (lane == 0) {
            int tg = tok0 + t;
            float s0 = (float)((double)Cs[t * NEXP + mi]  / rs);
            float s1 = (float)((double)Cs[t * NEXP + mi2] / rs);
            if (out_size >= 4 * NTOK) {
                out[(size_t)tg * 2 + 0] = s0;
                out[(size_t)tg * 2 + 1] = s1;
                out[(size_t)2 * NTOK + tg * 2 + 0] = (float)mi;
                out[(size_t)2 * NTOK + tg * 2 + 1] = (float)mi2;
            } else {
                out[(size_t)tg * 2 + 0] = s0;
                out[(size_t)tg * 2 + 1] = s1;
            }
        }
    }
}

// ---------------------------------------------------------------------------
extern "C" void kernel_launch(void* const* d_in, const int* in_sizes, int n_in,
                              void* d_out, int out_size)
{
    const float* X = (const float*)d_in[0];
    const float* W = (const float*)d_in[1];
    if (n_in >= 2 && in_sizes[0] == NEXP * HID) {   // defensive input-order check
        X = (const float*)d_in[1];
        W = (const float*)d_in[0];
    }
    cudaFuncSetAttribute(fused_router_kernel,
                         cudaFuncAttributeMaxDynamicSharedMemorySize, DSM_TOTAL);
    fused_router_kernel<<<GRIDB, TPB, DSM_TOTAL>>>(X, W, (float*)d_out, out_size);
}

// round 12
// speedup vs baseline: 1.8289x; 1.1384x over previous
#include <cuda_runtime.h>
#include <cuda_fp16.h>
#include <cstdint>

#define HID   2048
#define NEXP  64
#define NTOK  16384
#define SINK_TOL 1e-4
#define MAX_ITERS 512
#define GRIDB 128
#define TPB   512
#define NW    16
#define TOKB  128          // 16384 = 128 * 128 exactly
#define BKC   64           // k-chunk (elems) -> 128 B fp16 rows (SW128 atom)
#define NCHUNK (HID / BKC) // 32
#define CSTRIDE 16         // colsum pad: 128 B per expert column
#define WSCALE 64.0f       // exact pow2 pre-scale of W (fp16 subnormal avoidance)
#define WUNSCALE 0.015625f // 1/64, exact

// per-buffer tile offsets (bytes); buffer = 48 KB, two buffers
#define OF_A1  0
#define OF_A2  16384
#define OF_B1  32768
#define OF_B2  40960
#define BUFSZ  49152
#define DSM_TOTAL (2 * BUFSZ)   // 98304 B dynamic smem

extern "C" __device__ float __nv_expf(float);

__device__ __forceinline__ float frcp_approx(float x) {
    float r; asm("rcp.approx.f32 %0,%1;" : "=f"(r) : "f"(x)); return r;
}
__device__ __forceinline__ uint32_t smem_u32(const void* p) {
    uint32_t a;
    asm("{ .reg .u64 t; cvta.to.shared.u64 t, %1; cvt.u32.u64 %0, t; }" : "=r"(a) : "l"(p));
    return a;
}
#define SWZ(off) ((off) ^ (((off) >> 3) & 0x70))

__device__ __forceinline__ void ldsm_x4(uint32_t* r, uint32_t addr) {
    asm volatile("ldmatrix.sync.aligned.m8n8.x4.shared.b16 {%0,%1,%2,%3}, [%4];"
                 : "=r"(r[0]), "=r"(r[1]), "=r"(r[2]), "=r"(r[3]) : "r"(addr));
}
__device__ __forceinline__ void mma_f16(float* c, const uint32_t* a, const uint32_t* b) {
    asm volatile("mma.sync.aligned.m16n8k16.row.col.f32.f16.f16.f32 "
                 "{%0,%1,%2,%3}, {%4,%5,%6,%7}, {%8,%9}, {%0,%1,%2,%3};"
                 : "+f"(c[0]), "+f"(c[1]), "+f"(c[2]), "+f"(c[3])
                 : "r"(a[0]), "r"(a[1]), "r"(a[2]), "r"(a[3]), "r"(b[0]), "r"(b[1]));
}

// Scratch (static device arrays — no allocations).
__device__ unsigned long long g_bar = 0ULL;                      // grid barrier
__device__ double g_colsum[MAX_ITERS * NEXP * CSTRIDE];          // padded colsums

__device__ __forceinline__ void grid_barrier()
{
    __syncthreads();
    if (threadIdx.x == 0) {
        __threadfence();
        unsigned long long my = atomicAdd(&g_bar, 1ULL);
        unsigned long long target = (my / GRIDB + 1ULL) * GRIDB;
        for (;;) {
            unsigned long long cur;
            asm volatile("ld.global.acquire.gpu.u64 %0, [%1];" : "=l"(cur) : "l"(&g_bar));
            if (cur >= target) break;
        }
    }
    __syncthreads();
}

__device__ __forceinline__ double warp_tree_add64(double s)
{
#pragma unroll
    for (int off = 16; off; off >>= 1)
        s += __shfl_xor_sync(0xffffffffu, s, off);
    return s;
}

// 2-way fp16 split of 8 f32 (optionally pre-scaled), store 16B segs into two
// tiles spaced `spacing` bytes apart.
__device__ __forceinline__ void split2_store(char* base, int spacing, uint32_t sw,
                                             float4 v0, float4 v1, float scale)
{
    float f[8] = {v0.x, v0.y, v0.z, v0.w, v1.x, v1.y, v1.z, v1.w};
    unsigned short h1[8], h2[8];
#pragma unroll
    for (int i = 0; i < 8; i++) {
        float a = f[i] * scale;                 // exact for pow2 scale
        __half x1 = __float2half_rn(a);
        float r1 = a - __half2float(x1);        // exact
        __half x2 = __float2half_rn(r1);
        h1[i] = __half_as_ushort(x1);
        h2[i] = __half_as_ushort(x2);
    }
    uint4 q;
    q.x = h1[0] | ((uint32_t)h1[1] << 16); q.y = h1[2] | ((uint32_t)h1[3] << 16);
    q.z = h1[4] | ((uint32_t)h1[5] << 16); q.w = h1[6] | ((uint32_t)h1[7] << 16);
    *(uint4*)(base + sw) = q;
    q.x = h2[0] | ((uint32_t)h2[1] << 16); q.y = h2[2] | ((uint32_t)h2[3] << 16);
    q.z = h2[4] | ((uint32_t)h2[5] << 16); q.w = h2[6] | ((uint32_t)h2[7] << 16);
    *(uint4*)(base + spacing + sw) = q;
}

// ---------------------------------------------------------------------------
__global__ void __launch_bounds__(TPB, 1)
fused_router_kernel(const float* __restrict__ X, const float* __restrict__ W,
                    float* __restrict__ out, int out_size)
{
    extern __shared__ char dsm[];
    __shared__ float  warp_part[NW][NEXP];
    __shared__ double d1d[NEXP], d1pd[NEXP];
    __shared__ float  d1f[NEXP];
    __shared__ double s_err;

    const int tid  = threadIdx.x;
    const int bid  = blockIdx.x;
    const int lane = tid & 31;
    const int w    = tid >> 5;
    const int tok0 = bid * TOKB;
    const uint32_t smb = smem_u32(dsm);
    float* Cs = (float*)dsm;    // overlays buf0 after GEMM completes

    // zero this launch's colsum slots
    for (int i = bid * TPB + tid; i < MAX_ITERS * NEXP; i += GRIDB * TPB)
        g_colsum[(size_t)i * CSTRIDE] = 0.0;

    // ================= phase A: producer/consumer fp16-2-split HMMA ========
    const bool producer = (w >= 8);
    const int mt = (w & 7) >> 1;          // m-tile 0..3 (32 rows each)
    const int nh = w & 1;                 // n-half 0..1 (32 cols)

    // consumer A ldsm (m16 x4): rows mt*32+mi*16+(lane&15), koff (lane>>4)*16
    uint32_t aconst[2], amask[2];
#pragma unroll
    for (int mi = 0; mi < 2; mi++) {
        int arow = mt * 32 + mi * 16 + (lane & 15);
        aconst[mi] = (uint32_t)(arow * 128);
        amask[mi]  = (uint32_t)((arow & 7) << 4);
    }
    const uint32_t akoff = (uint32_t)((lane >> 4) * 16);
    // consumer B ldsm x4 merged over j pairs: jj in {0,1} covers j = 2jj, 2jj+1
    // lane->matrix: g=lane>>3: m0=(j,k0) m1=(j,k1) m2=(j+1,k0) m3=(j+1,k1)
    uint32_t bconst4[2];
#pragma unroll
    for (int jj = 0; jj < 2; jj++) {
        int brow = nh * 32 + (jj * 2 + ((lane >> 4) & 1)) * 8 + (lane & 7);
        bconst4[jj] = (uint32_t)(brow * 128);
    }
    const uint32_t bmask = (uint32_t)((lane & 7) << 4);
    const uint32_t bkoff = (uint32_t)(((lane >> 3) & 1) * 16);

    const uint32_t SA[2] = {OF_A1, OF_A2};
    const uint32_t SB[2] = {OF_B1, OF_B2};
    // products smallest-first: x2w2, x2w1, x1w2, x1w1
    const int PAI[4] = {1, 1, 0, 0};
    const int PBI[4] = {1, 0, 1, 0};

    // producer maps: A 1024 segs (4/thread), B 512 segs (2/thread)
    const int ptid = tid & 255;
    uint32_t asw_p[4]; size_t aoff_p[4];
    uint32_t bsw_p[2]; size_t boff_p[2];
#pragma unroll
    for (int j = 0; j < 4; j++) {
        int seg = ptid + j * 256;
        int row = seg >> 3, kq = (seg & 7) * 8;
        asw_p[j]  = SWZ((uint32_t)(row * 128 + kq * 2));
        aoff_p[j] = (size_t)(tok0 + row) * HID + kq;
    }
#pragma unroll
    for (int j = 0; j < 2; j++) {
        int seg = ptid + j * 256;
        int row = seg >> 3, kq = (seg & 7) * 8;
        bsw_p[j]  = SWZ((uint32_t)(row * 128 + kq * 2));
        boff_p[j] = (size_t)row * HID + kq;
    }

    float4 av[4][2], bvv[2][2];
    if (producer) {   // prefetch chunk 0
#pragma unroll
        for (int j = 0; j < 4; j++) {
            av[j][0] = *(const float4*)(X + aoff_p[j]);
            av[j][1] = *(const float4*)(X + aoff_p[j] + 4);
        }
#pragma unroll
        for (int j = 0; j < 2; j++) {
            bvv[j][0] = *(const float4*)(W + boff_p[j]);
            bvv[j][1] = *(const float4*)(W + boff_p[j] + 4);
        }
    }

    float hi[2][4][4];
#pragma unroll
    for (int mi = 0; mi < 2; mi++)
#pragma unroll
        for (int j = 0; j < 4; j++)
#pragma unroll
            for (int q = 0; q < 4; q++) hi[mi][j][q] = 0.f;

    for (int it = 0; it <= NCHUNK; it++) {
        if (producer) {
            if (it < NCHUNK) {
                char* base = dsm + (it & 1) * BUFSZ;
#pragma unroll
                for (int j = 0; j < 4; j++)
                    split2_store(base + OF_A1, 16384, asw_p[j], av[j][0], av[j][1], 1.0f);
#pragma unroll
                for (int j = 0; j < 2; j++)
                    split2_store(base + OF_B1, 8192, bsw_p[j], bvv[j][0], bvv[j][1], WSCALE);
                if (it + 1 < NCHUNK) {
                    int k0 = (it + 1) * BKC;
#pragma unroll
                    for (int j = 0; j < 4; j++) {
                        av[j][0] = *(const float4*)(X + aoff_p[j] + k0);
                        av[j][1] = *(const float4*)(X + aoff_p[j] + k0 + 4);
                    }
#pragma unroll
                    for (int j = 0; j < 2; j++) {
                        bvv[j][0] = *(const float4*)(W + boff_p[j] + k0);
                        bvv[j][1] = *(const float4*)(W + boff_p[j] + k0 + 4);
                    }
                }
            }
        } else if (it >= 1) {
            const uint32_t bb = smb + (uint32_t)(((it - 1) & 1) * BUFSZ);
            float accf[2][4][4];
#pragma unroll
            for (int mi = 0; mi < 2; mi++)
#pragma unroll
                for (int j = 0; j < 4; j++)
#pragma unroll
                    for (int q = 0; q < 4; q++) accf[mi][j][q] = 0.f;
#pragma unroll
            for (int ks = 0; ks < 4; ks++) {
                uint32_t kb_a = (uint32_t)(ks * 32) + akoff;
                uint32_t kb_b = (uint32_t)(ks * 32) + bkoff;
                uint32_t afr[2][2][4];      // [split][mi]
                uint32_t bfr[2][2][4];      // [split][jj] -> j=2jj (r0,r1), j=2jj+1 (r2,r3)
#pragma unroll
                for (int s = 0; s < 2; s++) {
#pragma unroll
                    for (int mi = 0; mi < 2; mi++)
                        ldsm_x4(afr[s][mi], bb + SA[s] + aconst[mi] + (kb_a ^ amask[mi]));
#pragma unroll
                    for (int jj = 0; jj < 2; jj++)
                        ldsm_x4(bfr[s][jj], bb + SB[s] + bconst4[jj] + (kb_b ^ bmask));
                }
#pragma unroll
                for (int p = 0; p < 4; p++)
#pragma unroll
                    for (int mi = 0; mi < 2; mi++)
#pragma unroll
                        for (int j = 0; j < 4; j++)
                            mma_f16(accf[mi][j], afr[PAI[p]][mi],
                                    &bfr[PBI[p]][j >> 1][(j & 1) * 2]);
            }
#pragma unroll
            for (int mi = 0; mi < 2; mi++)
#pragma unroll
                for (int j = 0; j < 4; j++)
#pragma unroll
                    for (int q = 0; q < 4; q++) hi[mi][j][q] += accf[mi][j][q];
        }
        __syncthreads();
    }

    // epilogue: unscale (exact pow2) then exp(logits) into Cs (overlays buf0)
    if (!producer) {
#pragma unroll
        for (int mi = 0; mi < 2; mi++) {
            int r0 = mt * 32 + mi * 16 + (lane >> 2);
#pragma unroll
            for (int j = 0; j < 4; j++) {
                int cc = nh * 32 + j * 8 + (lane & 3) * 2;
                float2 v0 = make_float2(__nv_expf(hi[mi][j][0] * WUNSCALE),
                                        __nv_expf(hi[mi][j][1] * WUNSCALE));
                float2 v1 = make_float2(__nv_expf(hi[mi][j][2] * WUNSCALE),
                                        __nv_expf(hi[mi][j][3] * WUNSCALE));
                *(float2*)&Cs[r0 * NEXP + cc]       = v0;
                *(float2*)&Cs[(r0 + 8) * NEXP + cc] = v1;
            }
        }
    }
    if (tid < NEXP) { d1d[tid] = 1.0; d1pd[tid] = 1.0; d1f[tid] = 1.f; }
    grid_barrier();   // Cs ready; colsum zeros globally visible

    // ================= phase B: Sinkhorn iterations (as R10) ===============
    const float  INVN0F = 1.0f / (float)NTOK;
    const float  EPSF   = 1e-8f;
    const double INVN1D = 1.0 / (double)NEXP;
    const double EPSD   = (double)1e-8f;
    const int    esl    = (tid < NEXP) ? ((tid + (bid << 2)) & 63) : 0;

    for (int it = 0; it < MAX_ITERS; it++) {
        float d1a = d1f[lane];
        float d1c = d1f[lane + 32];
        float p0 = 0.f, p1 = 0.f;
#pragma unroll
        for (int g = 0; g < 2; g++) {
            int tb = w + g * 64;
            float c0[4], c1[4], s[4];
#pragma unroll
            for (int q = 0; q < 4; q++) {
                int t = tb + q * NW;
                c0[q] = Cs[t * NEXP + lane];
                c1[q] = Cs[t * NEXP + lane + 32];
                s[q]  = fmaf(d1a, c0[q], d1c * c1[q]);
            }
#pragma unroll
            for (int off = 16; off; off >>= 1)
#pragma unroll
                for (int q = 0; q < 4; q++)
                    s[q] += __shfl_xor_sync(0xffffffffu, s[q], off);
#pragma unroll
            for (int q = 0; q < 4; q++) {
                float d0 = frcp_approx(s[q] + EPSF) * INVN0F;
                p0 = fmaf(d0, c0[q], p0);
                p1 = fmaf(d0, c1[q], p1);
            }
        }
        warp_part[w][lane]      = p0;
        warp_part[w][lane + 32] = p1;
        __syncthreads();
        if (tid < NEXP) {
            double sum = 0.0;
#pragma unroll
            for (int ww = 0; ww < NW; ww++) sum += (double)warp_part[ww][esl];
            atomicAdd(&g_colsum[((size_t)it * NEXP + esl) * CSTRIDE], sum);
        }
        grid_barrier();

        if (w == 0) {
            double cs0 = g_colsum[((size_t)it * NEXP + lane) * CSTRIDE];
            double cs1 = g_colsum[((size_t)it * NEXP + lane + 32) * CSTRIDE];
            double v0  = INVN1D / (cs0 + EPSD);
            double v1  = INVN1D / (cs1 + EPSD);
            double o0  = d1d[lane];
            double o1  = d1d[lane + 32];
            double s   = warp_tree_add64(fabs(o0 - v0) + fabs(o1 - v1));
            d1pd[lane]      = o0;  d1pd[lane + 32] = o1;
            d1d[lane]       = v0;  d1d[lane + 32]  = v1;
            d1f[lane]       = (float)v0;
            d1f[lane + 32]  = (float)v1;
            if (lane == 0) s_err = s * INVN1D;
        }
        __syncthreads();
        if (s_err <= SINK_TOL) break;
    }

    // ================= phase C: top-2 (fp64) + softmax-gather ==============
    const double INVN0D = 1.0 / (double)NTOK;
    double d1a = d1d[lane],  d1c = d1d[lane + 32];
    double dpa = d1pd[lane], dpc = d1pd[lane + 32];
    for (int t = w; t < TOKB; t += NW) {
        double c0 = (double)Cs[t * NEXP + lane];
        double c1 = (double)Cs[t * NEXP + lane + 32];
        double sr = warp_tree_add64(dpa * c0 + dpc * c1);
        double rs = warp_tree_add64(c0 + c1);
        double d0 = INVN0D / (sr + EPSD);
        double v0 = (d1a * c0) * d0;
        double v1 = (d1c * c1) * d0;

        double mv; int mi;
        if (v0 >= v1) { mv = v0; mi = lane; } else { mv = v1; mi = lane + 32; }
#pragma unroll
        for (int off = 16; off; off >>= 1) {
            double ov = __shfl_xor_sync(0xffffffffu, mv, off);
            int    oi = __shfl_xor_sync(0xffffffffu, mi, off);
            if (ov > mv || (ov == mv && oi < mi)) { mv = ov; mi = oi; }
        }
        double u0 = (lane      == mi) ? -1e308 : v0;
        double u1 = (lane + 32 == mi) ? -1e308 : v1;
        double mv2; int mi2;
        if (u0 >= u1) { mv2 = u0; mi2 = lane; } else { mv2 = u1; mi2 = lane + 32; }
#pragma unroll
        for (int off = 16; off; off >>= 1) {
            double ov = __shfl_xor_sync(0xffffffffu, mv2, off);
            int    oi = __shfl_xor_sync(0xffffffffu, mi2, off);
            if (ov > mv2 || (ov == mv2 && oi < mi2)) { mv2 = ov; mi2 = oi; }
        }

        if (lane == 0) {
            int tg = tok0 + t;
            float s0 = (float)((double)Cs[t * NEXP + mi]  / rs);
            float s1 = (float)((double)Cs[t * NEXP + mi2] / rs);
            if (out_size >= 4 * NTOK) {
                out[(size_t)tg * 2 + 0] = s0;
                out[(size_t)tg * 2 + 1] = s1;
                out[(size_t)2 * NTOK + tg * 2 + 0] = (float)mi;
                out[(size_t)2 * NTOK + tg * 2 + 1] = (float)mi2;
            } else {
                out[(size_t)tg * 2 + 0] = s0;
                out[(size_t)tg * 2 + 1] = s1;
            }
        }
    }
}

// ---------------------------------------------------------------------------
extern "C" void kernel_launch(void* const* d_in, const int* in_sizes, int n_in,
                              void* d_out, int out_size)
{
    const float* X = (const float*)d_in[0];
    const float* W = (const float*)d_in[1];
    if (n_in >= 2 && in_sizes[0] == NEXP * HID) {   // defensive input-order check
        X = (const float*)d_in[1];
        W = (const float*)d_in[0];
    }
    cudaFuncSetAttribute(fused_router_kernel,
                         cudaFuncAttributeMaxDynamicSharedMemorySize, DSM_TOTAL);
    fused_router_kernel<<<GRIDB, TPB, DSM_TOTAL>>>(X, W, (float*)d_out, out_size);
}

// round 13
// speedup vs baseline: 1.9283x; 1.0543x over previous
#include <cuda_runtime.h>
#include <cuda_fp16.h>
#include <cstdint>

#define HID   2048
#define NEXP  64
#define NTOK  16384
#define SINK_TOL 1e-4
#define MAX_ITERS 512
#define GRIDB 128
#define TPB   512
#define NW    16
#define TOKB  128          // 16384 = 128 * 128 exactly
#define BKC   64           // k-chunk (elems) -> 128 B fp16 rows (SW128 atom)
#define NCHUNK (HID / BKC) // 32
#define CSTRIDE 16         // colsum pad: 128 B per expert column
#define WSCALE 64.0f       // exact pow2 pre-scale of W (fp16 subnormal avoidance)
#define WUNSCALE 0.015625f // 1/64, exact

// per-buffer tile offsets (bytes); buffer = 48 KB, two buffers
#define OF_A1  0
#define OF_A2  16384
#define OF_B1  32768
#define OF_B2  40960
#define BUFSZ  49152
#define DSM_TOTAL (2 * BUFSZ)   // 98304 B dynamic smem

extern "C" __device__ float __nv_expf(float);

__device__ __forceinline__ float frcp_approx(float x) {
    float r; asm("rcp.approx.f32 %0,%1;" : "=f"(r) : "f"(x)); return r;
}
__device__ __forceinline__ uint32_t smem_u32(const void* p) {
    uint32_t a;
    asm("{ .reg .u64 t; cvta.to.shared.u64 t, %1; cvt.u32.u64 %0, t; }" : "=r"(a) : "l"(p));
    return a;
}
#define SWZ(off) ((off) ^ (((off) >> 3) & 0x70))

__device__ __forceinline__ void ldsm_x4(uint32_t* r, uint32_t addr) {
    asm volatile("ldmatrix.sync.aligned.m8n8.x4.shared.b16 {%0,%1,%2,%3}, [%4];"
                 : "=r"(r[0]), "=r"(r[1]), "=r"(r[2]), "=r"(r[3]) : "r"(addr));
}
__device__ __forceinline__ void mma_f16(float* c, const uint32_t* a, const uint32_t* b) {
    asm volatile("mma.sync.aligned.m16n8k16.row.col.f32.f16.f16.f32 "
                 "{%0,%1,%2,%3}, {%4,%5,%6,%7}, {%8,%9}, {%0,%1,%2,%3};"
                 : "+f"(c[0]), "+f"(c[1]), "+f"(c[2]), "+f"(c[3])
                 : "r"(a[0]), "r"(a[1]), "r"(a[2]), "r"(a[3]), "r"(b[0]), "r"(b[1]));
}

// Scratch (static device arrays — no allocations).
__device__ unsigned long long g_bar = 0ULL;                      // grid barrier
__device__ double g_colsum[MAX_ITERS * NEXP * CSTRIDE];          // padded colsums

__device__ __forceinline__ void grid_barrier()
{
    __syncthreads();
    if (threadIdx.x == 0) {
        __threadfence();
        unsigned long long my = atomicAdd(&g_bar, 1ULL);
        unsigned long long target = (my / GRIDB + 1ULL) * GRIDB;
        for (;;) {
            unsigned long long cur;
            asm volatile("ld.global.acquire.gpu.u64 %0, [%1];" : "=l"(cur) : "l"(&g_bar));
            if (cur >= target) break;
        }
    }
    __syncthreads();
}

__device__ __forceinline__ double warp_tree_add64(double s)
{
#pragma unroll
    for (int off = 16; off; off >>= 1)
        s += __shfl_xor_sync(0xffffffffu, s, off);
    return s;
}

// 2-way fp16 split of 8 f32 (optionally pre-scaled), store 16B segs into two
// tiles spaced `spacing` bytes apart.
__device__ __forceinline__ void split2_store(char* base, int spacing, uint32_t sw,
                                             float4 v0, float4 v1, float scale)
{
    float f[8] = {v0.x, v0.y, v0.z, v0.w, v1.x, v1.y, v1.z, v1.w};
    unsigned short h1[8], h2[8];
#pragma unroll
    for (int i = 0; i < 8; i++) {
        float a = f[i] * scale;                 // exact for pow2 scale
        __half x1 = __float2half_rn(a);
        float r1 = a - __half2float(x1);        // exact
        __half x2 = __float2half_rn(r1);
        h1[i] = __half_as_ushort(x1);
        h2[i] = __half_as_ushort(x2);
    }
    uint4 q;
    q.x = h1[0] | ((uint32_t)h1[1] << 16); q.y = h1[2] | ((uint32_t)h1[3] << 16);
    q.z = h1[4] | ((uint32_t)h1[5] << 16); q.w = h1[6] | ((uint32_t)h1[7] << 16);
    *(uint4*)(base + sw) = q;
    q.x = h2[0] | ((uint32_t)h2[1] << 16); q.y = h2[2] | ((uint32_t)h2[3] << 16);
    q.z = h2[4] | ((uint32_t)h2[5] << 16); q.w = h2[6] | ((uint32_t)h2[7] << 16);
    *(uint4*)(base + spacing + sw) = q;
}

// ---------------------------------------------------------------------------
__global__ void __launch_bounds__(TPB, 1)
fused_router_kernel(const float* __restrict__ X, const float* __restrict__ W,
                    float* __restrict__ out, int out_size)
{
    extern __shared__ char dsm[];
    __shared__ float  warp_part[NW][NEXP];
    __shared__ double d1d[NEXP], d1pd[NEXP];
    __shared__ float  d1f[NEXP];
    __shared__ double s_err;

    const int tid  = threadIdx.x;
    const int bid  = blockIdx.x;
    const int lane = tid & 31;
    const int w    = tid >> 5;
    const int tok0 = bid * TOKB;
    const uint32_t smb = smem_u32(dsm);
    float* Cs = (float*)dsm;    // overlays buf0 after GEMM completes

    // zero this launch's colsum slots
    for (int i = bid * TPB + tid; i < MAX_ITERS * NEXP; i += GRIDB * TPB)
        g_colsum[(size_t)i * CSTRIDE] = 0.0;

    // ================= phase A: producer/consumer fp16-2-split HMMA ========
    // 3 products: x2w1, x1w2, x1w1 (x2w2 dropped: <=2^-22 per-term, ~1.4e-7 logit noise)
    const bool producer = (w >= 8);
    const int mt = (w & 7) >> 1;          // m-tile 0..3 (32 rows each)
    const int nh = w & 1;                 // n-half 0..1 (32 cols)

    uint32_t aconst[2], amask[2];
#pragma unroll
    for (int mi = 0; mi < 2; mi++) {
        int arow = mt * 32 + mi * 16 + (lane & 15);
        aconst[mi] = (uint32_t)(arow * 128);
        amask[mi]  = (uint32_t)((arow & 7) << 4);
    }
    const uint32_t akoff = (uint32_t)((lane >> 4) * 16);
    uint32_t bconst4[2];
#pragma unroll
    for (int jj = 0; jj < 2; jj++) {
        int brow = nh * 32 + (jj * 2 + ((lane >> 4) & 1)) * 8 + (lane & 7);
        bconst4[jj] = (uint32_t)(brow * 128);
    }
    const uint32_t bmask = (uint32_t)((lane & 7) << 4);
    const uint32_t bkoff = (uint32_t)(((lane >> 3) & 1) * 16);

    const uint32_t SA[2] = {OF_A1, OF_A2};
    const uint32_t SB[2] = {OF_B1, OF_B2};
    // products smallest-first: x2w1, x1w2, x1w1
    const int PAI[3] = {1, 0, 0};
    const int PBI[3] = {0, 1, 0};

    const int ptid = tid & 255;
    uint32_t asw_p[4]; size_t aoff_p[4];
    uint32_t bsw_p[2]; size_t boff_p[2];
#pragma unroll
    for (int j = 0; j < 4; j++) {
        int seg = ptid + j * 256;
        int row = seg >> 3, kq = (seg & 7) * 8;
        asw_p[j]  = SWZ((uint32_t)(row * 128 + kq * 2));
        aoff_p[j] = (size_t)(tok0 + row) * HID + kq;
    }
#pragma unroll
    for (int j = 0; j < 2; j++) {
        int seg = ptid + j * 256;
        int row = seg >> 3, kq = (seg & 7) * 8;
        bsw_p[j]  = SWZ((uint32_t)(row * 128 + kq * 2));
        boff_p[j] = (size_t)row * HID + kq;
    }

    float4 av[4][2], bvv[2][2];
    if (producer) {   // prefetch chunk 0
#pragma unroll
        for (int j = 0; j < 4; j++) {
            av[j][0] = *(const float4*)(X + aoff_p[j]);
            av[j][1] = *(const float4*)(X + aoff_p[j] + 4);
        }
#pragma unroll
        for (int j = 0; j < 2; j++) {
            bvv[j][0] = *(const float4*)(W + boff_p[j]);
            bvv[j][1] = *(const float4*)(W + boff_p[j] + 4);
        }
    }

    float hi[2][4][4];
#pragma unroll
    for (int mi = 0; mi < 2; mi++)
#pragma unroll
        for (int j = 0; j < 4; j++)
#pragma unroll
            for (int q = 0; q < 4; q++) hi[mi][j][q] = 0.f;

    for (int it = 0; it <= NCHUNK; it++) {
        if (producer) {
            if (it < NCHUNK) {
                char* base = dsm + (it & 1) * BUFSZ;
#pragma unroll
                for (int j = 0; j < 4; j++)
                    split2_store(base + OF_A1, 16384, asw_p[j], av[j][0], av[j][1], 1.0f);
#pragma unroll
                for (int j = 0; j < 2; j++)
                    split2_store(base + OF_B1, 8192, bsw_p[j], bvv[j][0], bvv[j][1], WSCALE);
                if (it + 1 < NCHUNK) {
                    int k0 = (it + 1) * BKC;
#pragma unroll
                    for (int j = 0; j < 4; j++) {
                        av[j][0] = *(const float4*)(X + aoff_p[j] + k0);
                        av[j][1] = *(const float4*)(X + aoff_p[j] + k0 + 4);
                    }
#pragma unroll
                    for (int j = 0; j < 2; j++) {
                        bvv[j][0] = *(const float4*)(W + boff_p[j] + k0);
                        bvv[j][1] = *(const float4*)(W + boff_p[j] + k0 + 4);
                    }
                }
            }
        } else if (it >= 1) {
            const uint32_t bb = smb + (uint32_t)(((it - 1) & 1) * BUFSZ);
            float accf[2][4][4];
#pragma unroll
            for (int mi = 0; mi < 2; mi++)
#pragma unroll
                for (int j = 0; j < 4; j++)
#pragma unroll
                    for (int q = 0; q < 4; q++) accf[mi][j][q] = 0.f;
#pragma unroll
            for (int ks = 0; ks < 4; ks++) {
                uint32_t kb_a = (uint32_t)(ks * 32) + akoff;
                uint32_t kb_b = (uint32_t)(ks * 32) + bkoff;
                uint32_t afr[2][2][4];      // [split][mi]
                uint32_t bfr[2][2][4];      // [split][jj]
#pragma unroll
                for (int s = 0; s < 2; s++) {
#pragma unroll
                    for (int mi = 0; mi < 2; mi++)
                        ldsm_x4(afr[s][mi], bb + SA[s] + aconst[mi] + (kb_a ^ amask[mi]));
#pragma unroll
                    for (int jj = 0; jj < 2; jj++)
                        ldsm_x4(bfr[s][jj], bb + SB[s] + bconst4[jj] + (kb_b ^ bmask));
                }
#pragma unroll
                for (int p = 0; p < 3; p++)
#pragma unroll
                    for (int mi = 0; mi < 2; mi++)
#pragma unroll
                        for (int j = 0; j < 4; j++)
                            mma_f16(accf[mi][j], afr[PAI[p]][mi],
                                    &bfr[PBI[p]][j >> 1][(j & 1) * 2]);
            }
#pragma unroll
            for (int mi = 0; mi < 2; mi++)
#pragma unroll
                for (int j = 0; j < 4; j++)
#pragma unroll
                    for (int q = 0; q < 4; q++) hi[mi][j][q] += accf[mi][j][q];
        }
        __syncthreads();
    }

    // epilogue: unscale (exact pow2) then exp(logits) into Cs (overlays buf0)
    if (!producer) {
#pragma unroll
        for (int mi = 0; mi < 2; mi++) {
            int r0 = mt * 32 + mi * 16 + (lane >> 2);
#pragma unroll
            for (int j = 0; j < 4; j++) {
                int cc = nh * 32 + j * 8 + (lane & 3) * 2;
                float2 v0 = make_float2(__nv_expf(hi[mi][j][0] * WUNSCALE),
                                        __nv_expf(hi[mi][j][1] * WUNSCALE));
                float2 v1 = make_float2(__nv_expf(hi[mi][j][2] * WUNSCALE),
                                        __nv_expf(hi[mi][j][3] * WUNSCALE));
                *(float2*)&Cs[r0 * NEXP + cc]       = v0;
                *(float2*)&Cs[(r0 + 8) * NEXP + cc] = v1;
            }
        }
    }
    if (tid < NEXP) { d1d[tid] = 1.0; d1pd[tid] = 1.0; d1f[tid] = 1.f; }
    grid_barrier();   // Cs ready; colsum zeros globally visible

    // ================= phase B: Sinkhorn iterations ========================
    const float  INVN0F = 1.0f / (float)NTOK;   // 2^-14 exact
    const float  INVN1F = 0.015625f;            // 2^-6 exact
    const float  EPSF   = 1e-8f;
    const double INVN1D = 1.0 / (double)NEXP;
    const double EPSD   = (double)1e-8f;
    const int    esl    = (tid < NEXP) ? ((tid + (bid << 2)) & 63) : 0;

    for (int it = 0; it < MAX_ITERS; it++) {
        float d1a = d1f[lane];
        float d1c = d1f[lane + 32];
        float p0 = 0.f, p1 = 0.f;
        // 8-way interleaved shuffle trees; accumulation in original token order
        {
            float c0[8], c1[8], s[8];
#pragma unroll
            for (int q = 0; q < 8; q++) {
                int t = w + q * NW;
                c0[q] = Cs[t * NEXP + lane];
                c1[q] = Cs[t * NEXP + lane + 32];
                s[q]  = fmaf(d1a, c0[q], d1c * c1[q]);
            }
#pragma unroll
            for (int off = 16; off; off >>= 1)
#pragma unroll
                for (int q = 0; q < 8; q++)
                    s[q] += __shfl_xor_sync(0xffffffffu, s[q], off);
#pragma unroll
            for (int q = 0; q < 8; q++) {
                float d0 = frcp_approx(s[q] + EPSF) * INVN0F;
                p0 = fmaf(d0, c0[q], p0);
                p1 = fmaf(d0, c1[q], p1);
            }
        }
        warp_part[w][lane]      = p0;
        warp_part[w][lane + 32] = p1;
        __syncthreads();
        if (tid < NEXP) {
            double sum = 0.0;
#pragma unroll
            for (int ww = 0; ww < NW; ww++) sum += (double)warp_part[ww][esl];
            atomicAdd(&g_colsum[((size_t)it * NEXP + esl) * CSTRIDE], sum);
        }
        grid_barrier();

        if (w == 0) {
            double cs0 = g_colsum[((size_t)it * NEXP + lane) * CSTRIDE];
            double cs1 = g_colsum[((size_t)it * NEXP + lane + 32) * CSTRIDE];
            // fast f32 mirror first — unblocks the next row pass ASAP
            d1f[lane]      = frcp_approx((float)cs0 + EPSF) * INVN1F;
            d1f[lane + 32] = frcp_approx((float)cs1 + EPSF) * INVN1F;
            // f64 master via rcp + 2 Newton steps (~1 ulp; reference d1 is f32)
            double x0 = cs0 + EPSD, x1 = cs1 + EPSD;
            double r0 = (double)frcp_approx((float)x0);
            double r1 = (double)frcp_approx((float)x1);
            r0 = r0 * (2.0 - x0 * r0); r0 = r0 * (2.0 - x0 * r0);
            r1 = r1 * (2.0 - x1 * r1); r1 = r1 * (2.0 - x1 * r1);
            double v0 = INVN1D * r0, v1 = INVN1D * r1;
            double o0 = d1d[lane], o1 = d1d[lane + 32];
            double s  = warp_tree_add64(fabs(o0 - v0) + fabs(o1 - v1));
            d1pd[lane]      = o0;  d1pd[lane + 32] = o1;
            d1d[lane]       = v0;  d1d[lane + 32]  = v1;
            if (lane == 0) s_err = s * INVN1D;
        }
        __syncthreads();
        if (s_err <= SINK_TOL) break;
    }

    // ================= phase C: top-2 (fp64) + softmax-gather ==============
    const double INVN0D = 1.0 / (double)NTOK;
    double d1a = d1d[lane],  d1c = d1d[lane + 32];
    double dpa = d1pd[lane], dpc = d1pd[lane + 32];
    for (int t = w; t < TOKB; t += NW) {
        double c0 = (double)Cs[t * NEXP + lane];
        double c1 = (double)Cs[t * NEXP + lane + 32];
        double sr = warp_tree_add64(dpa * c0 + dpc * c1);
        double rs = warp_tree_add64(c0 + c1);
        double d0 = INVN0D / (sr + EPSD);
        double v0 = (d1a * c0) * d0;
        double v1 = (d1c * c1) * d0;

        double mv; int mi;
        if (v0 >= v1) { mv = v0; mi = lane; } else { mv = v1; mi = lane + 32; }
#pragma unroll
        for (int off = 16; off; off >>= 1) {
            double ov = __shfl_xor_sync(0xffffffffu, mv, off);
            int    oi = __shfl_xor_sync(0xffffffffu, mi, off);
            if (ov > mv || (ov == mv && oi < mi)) { mv = ov; mi = oi; }
        }
        double u0 = (lane      == mi) ? -1e308 : v0;
        double u1 = (lane + 32 == mi) ? -1e308 : v1;
        double mv2; int mi2;
        if (u0 >= u1) { mv2 = u0; mi2 = lane; } else { mv2 = u1; mi2 = lane + 32; }
#pragma unroll
        for (int off = 16; off; off >>= 1) {
            double ov = __shfl_xor_sync(0xffffffffu, mv2, off);
            int    oi = __shfl_xor_sync(0xffffffffu, mi2, off);
            if (ov > mv2 || (ov == mv2 && oi < mi2)) { mv2 = ov; mi2 = oi; }
        }

        if (lane == 0) {
            int tg = tok0 + t;
            float s0 = (float)((double)Cs[t * NEXP + mi]  / rs);
            float s1 = (float)((double)Cs[t * NEXP + mi2] / rs);
            if (out_size >= 4 * NTOK) {
                out[(size_t)tg * 2 + 0] = s0;
                out[(size_t)tg * 2 + 1] = s1;
                out[(size_t)2 * NTOK + tg * 2 + 0] = (float)mi;
                out[(size_t)2 * NTOK + tg * 2 + 1] = (float)mi2;
            } else {
                out[(size_t)tg * 2 + 0] = s0;
                out[(size_t)tg * 2 + 1] = s1;
            }
        }
    }
}

// ---------------------------------------------------------------------------
extern "C" void kernel_launch(void* const* d_in, const int* in_sizes, int n_in,
                              void* d_out, int out_size)
{
    const float* X = (const float*)d_in[0];
    const float* W = (const float*)d_in[1];
    if (n_in >= 2 && in_sizes[0] == NEXP * HID) {   // defensive input-order check
        X = (const float*)d_in[1];
        W = (const float*)d_in[0];
    }
    cudaFuncSetAttribute(fused_router_kernel,
                         cudaFuncAttributeMaxDynamicSharedMemorySize, DSM_TOTAL);
    fused_router_kernel<<<GRIDB, TPB, DSM_TOTAL>>>(X, W, (float*)d_out, out_size);
}